// round 13
// baseline (speedup 1.0000x reference)
#include <cuda_runtime.h>
#include <cuda_bf16.h>
#include <math.h>

#define B_    2
#define S_    2048
#define D_    768
#define H_    12
#define DEP_  64
#define BH_   (B_*H_)            // 24
#define MROWS (B_*S_)            // 4096
#define KP_   384                // 768/2 pairs
#define OUT_ELEMS (B_*S_*D_)     // 3145728
#define ATTN_ELEMS (BH_*S_*S_)   // 100663296
#define NCHUNK 8

#define DYN_SMEM_BYTES 61440     // 15360 words

// ---- scratch (alloc-free, __device__ globals) ----
__device__ unsigned g_Xh[MROWS*KP_],  g_Xl[MROWS*KP_];    // presplit input (reused q/k/v)
__device__ unsigned g_Wh[D_*KP_],     g_Wl[D_*KP_];       // presplit weight (reused)
__device__ unsigned g_Qph[BH_*S_*32], g_Qpl[BH_*S_*32];   // Q proj, pair layout
__device__ unsigned g_Kph[BH_*S_*32], g_Kpl[BH_*S_*32];   // K proj, pair layout
__device__ float    g_Vp[BH_*S_*DEP_];                    // V proj fp32
__device__ unsigned g_Vth[BH_*DEP_*(S_/2)];               // V split, d-major
__device__ unsigned g_Vtl[BH_*DEP_*(S_/2)];
__device__ unsigned g_Ch[MROWS*KP_],  g_Cl[MROWS*KP_];    // ctx out, pair layout
__device__ float g_rowmax[BH_*S_];
__device__ float g_rowinv[BH_*S_];
__device__ float g_cmax[BH_*S_*NCHUNK];
__device__ float g_csum[BH_*S_*NCHUNK];
__device__ float g_attn_scratch[ATTN_ELEMS];

__device__ __forceinline__ float neg_inf() { return __int_as_float(0xff800000); }

__device__ __forceinline__ void split2(float x, float y, unsigned& h, unsigned& l) {
    __nv_bfloat162 hv = __floats2bfloat162_rn(x, y);
    float2 hf = __bfloat1622float2(hv);
    __nv_bfloat162 lv = __floats2bfloat162_rn(x - hf.x, y - hf.y);
    h = *(unsigned*)&hv;
    l = *(unsigned*)&lv;
}

__device__ __forceinline__ void mma16(float* c,
                                      unsigned a0, unsigned a1, unsigned a2, unsigned a3,
                                      unsigned b0, unsigned b1) {
    asm volatile(
        "mma.sync.aligned.m16n8k16.row.col.f32.bf16.bf16.f32 "
        "{%0,%1,%2,%3}, {%4,%5,%6,%7}, {%8,%9}, {%0,%1,%2,%3};\n"
        : "+f"(c[0]), "+f"(c[1]), "+f"(c[2]), "+f"(c[3])
        : "r"(a0), "r"(a1), "r"(a2), "r"(a3), "r"(b0), "r"(b1));
}

__device__ __forceinline__ void ldsm_x4(unsigned* r, const void* p) {
    unsigned addr = (unsigned)__cvta_generic_to_shared(p);
    asm volatile("ldmatrix.sync.aligned.m8n8.x4.shared.b16 {%0,%1,%2,%3}, [%4];"
        : "=r"(r[0]), "=r"(r[1]), "=r"(r[2]), "=r"(r[3]) : "r"(addr));
}

__device__ __forceinline__ void cp16(void* dst, const void* src) {
    unsigned d = (unsigned)__cvta_generic_to_shared(dst);
    asm volatile("cp.async.cg.shared.global [%0], [%1], 16;"
                 :: "r"(d), "l"(src) : "memory");
}
#define CP_COMMIT() asm volatile("cp.async.commit_group;" ::: "memory")
#define CP_WAIT0()  asm volatile("cp.async.wait_group 0;" ::: "memory")

// ======================================================================
// presplit: fp32 array -> hi/lo bf16-pair arrays. 4 pairs per thread.
// ======================================================================
__global__ __launch_bounds__(256)
void presplit(const float* __restrict__ src,
              unsigned* __restrict__ ph, unsigned* __restrict__ pl, int npairs)
{
    const int i = (blockIdx.x * 256 + threadIdx.x) * 4;
    if (i >= npairs) return;
    float4 a = *(const float4*)(src + 2*i);
    float4 b = *(const float4*)(src + 2*i + 4);
    uint4 h, l;
    split2(a.x, a.y, h.x, l.x);
    split2(a.z, a.w, h.y, l.y);
    split2(b.x, b.y, h.z, l.z);
    split2(b.z, b.w, h.w, l.w);
    *(uint4*)(ph + i) = h;
    *(uint4*)(pl + i) = l;
}

// ======================================================================
// GEMM on pre-split operands, cp.async pipeline.
// C = alpha*(X @ W^T + bias); 128m x 64n tile, slab = 16 pairs (32 k).
// mode 0: fp32 [M,N]; mode 1: fp32 head-split; mode 2: pair head-split.
// dyn smem stage st (7680 words): AH @ st*7680, AL +2560, BH +5120, BL +6400
// ======================================================================
__global__ __launch_bounds__(256, 2)
void gemm_ps(const unsigned* __restrict__ Xh, const unsigned* __restrict__ Xl,
             const unsigned* __restrict__ Wh, const unsigned* __restrict__ Wl,
             const float* __restrict__ bias,
             float* __restrict__ Cf,
             unsigned* __restrict__ Ch, unsigned* __restrict__ Cl,
             int Kp, int N, float alpha, int mode)
{
    extern __shared__ unsigned dsm[];

    const int t = threadIdx.x, wid = t >> 5, lane = t & 31;
    const int gid = lane >> 2, tig = lane & 3;
    const int n0 = blockIdx.x * 64, m0 = blockIdx.y * 128;
    const int wm = (wid & 3) * 32, wn = (wid >> 2) * 32;

    const int a_r = lane & 15, a_c = ((lane >> 4) & 1) * 4;
    const int b_r = (lane & 7) + ((lane >> 4) & 1) * 8;
    const int b_c = ((lane >> 3) & 1) * 4;

    const int ar = t >> 1, alg = t & 1;    // A cp: row, half (8 pairs)
    const int br2 = t >> 2, bg2 = t & 3;   // B cp: row, quarter (4 pairs)

    const unsigned* XhP = Xh + (size_t)(m0 + ar) * Kp + alg * 8;
    const unsigned* XlP = Xl + (size_t)(m0 + ar) * Kp + alg * 8;
    const unsigned* WhP = Wh + (size_t)(n0 + br2) * Kp + bg2 * 4;
    const unsigned* WlP = Wl + (size_t)(n0 + br2) * Kp + bg2 * 4;

    float acc[2][4][4];
#pragma unroll
    for (int i = 0; i < 2; i++)
#pragma unroll
        for (int j = 0; j < 4; j++)
#pragma unroll
            for (int q = 0; q < 4; q++) acc[i][j][q] = 0.0f;

    const int NS = Kp / 16;

    // prologue: slab 0 -> stage 0
    cp16(dsm        + ar*20 + alg*8,     XhP);
    cp16(dsm        + ar*20 + alg*8 + 4, XhP + 4);
    cp16(dsm + 2560 + ar*20 + alg*8,     XlP);
    cp16(dsm + 2560 + ar*20 + alg*8 + 4, XlP + 4);
    cp16(dsm + 5120 + br2*20 + bg2*4,    WhP);
    cp16(dsm + 6400 + br2*20 + bg2*4,    WlP);
    CP_COMMIT();

#pragma unroll 1
    for (int s = 0; s < NS; s++) {
        const int st = s & 1;
        const unsigned base = st * 7680;

        CP_WAIT0();
        __syncthreads();

        if (s + 1 < NS) {
            const unsigned nb = (st ^ 1) * 7680;
            const int kp = (s + 1) * 16;
            cp16(dsm + nb        + ar*20 + alg*8,     XhP + kp);
            cp16(dsm + nb        + ar*20 + alg*8 + 4, XhP + kp + 4);
            cp16(dsm + nb + 2560 + ar*20 + alg*8,     XlP + kp);
            cp16(dsm + nb + 2560 + ar*20 + alg*8 + 4, XlP + kp + 4);
            cp16(dsm + nb + 5120 + br2*20 + bg2*4,    WhP + kp);
            cp16(dsm + nb + 6400 + br2*20 + bg2*4,    WlP + kp);
            CP_COMMIT();
        }

#pragma unroll
        for (int step = 0; step < 2; step++) {
            const int kc = step * 8;
            unsigned ah[2][4], al[2][4], bhf[2][4], blf[2][4];
#pragma unroll
            for (int mt = 0; mt < 2; mt++) {
                ldsm_x4(ah[mt], dsm + base        + (wm + mt*16 + a_r)*20 + kc + a_c);
                ldsm_x4(al[mt], dsm + base + 2560 + (wm + mt*16 + a_r)*20 + kc + a_c);
            }
#pragma unroll
            for (int np = 0; np < 2; np++) {
                ldsm_x4(bhf[np], dsm + base + 5120 + (wn + np*16 + b_r)*20 + kc + b_c);
                ldsm_x4(blf[np], dsm + base + 6400 + (wn + np*16 + b_r)*20 + kc + b_c);
            }
#pragma unroll
            for (int nt = 0; nt < 4; nt++) {
                const unsigned bh0 = bhf[nt>>1][(nt&1)*2], bh1 = bhf[nt>>1][(nt&1)*2+1];
                const unsigned bl0 = blf[nt>>1][(nt&1)*2], bl1 = blf[nt>>1][(nt&1)*2+1];
#pragma unroll
                for (int mt = 0; mt < 2; mt++) {
                    mma16(acc[mt][nt], ah[mt][0],ah[mt][1],ah[mt][2],ah[mt][3], bh0, bh1);
                    mma16(acc[mt][nt], ah[mt][0],ah[mt][1],ah[mt][2],ah[mt][3], bl0, bl1);
                    mma16(acc[mt][nt], al[mt][0],al[mt][1],al[mt][2],al[mt][3], bh0, bh1);
                }
            }
        }
    }

    const int hh = n0 / DEP_;
#pragma unroll
    for (int mt = 0; mt < 2; mt++) {
#pragma unroll
        for (int nt = 0; nt < 4; nt++) {
            const int r0 = m0 + wm + mt*16 + gid;
            const int r1 = r0 + 8;
            const int c  = n0 + wn + nt*8 + tig*2;
            const float b0v = bias[c], b1v = bias[c+1];
            const float v00 = alpha * (acc[mt][nt][0] + b0v);
            const float v01 = alpha * (acc[mt][nt][1] + b1v);
            const float v10 = alpha * (acc[mt][nt][2] + b0v);
            const float v11 = alpha * (acc[mt][nt][3] + b1v);
            if (mode == 0) {
                *(float2*)(Cf + (size_t)r0 * N + c) = make_float2(v00, v01);
                *(float2*)(Cf + (size_t)r1 * N + c) = make_float2(v10, v11);
            } else {
                const int dd = c - n0;
                const int b0_ = r0 / S_, s0 = r0 % S_;
                const int b1_ = r1 / S_, s1 = r1 % S_;
                if (mode == 1) {
                    *(float2*)(Cf + (((size_t)(b0_*H_ + hh))*S_ + s0)*DEP_ + dd)
                        = make_float2(v00, v01);
                    *(float2*)(Cf + (((size_t)(b1_*H_ + hh))*S_ + s1)*DEP_ + dd)
                        = make_float2(v10, v11);
                } else {
                    unsigned h0, l0, h1, l1;
                    split2(v00, v01, h0, l0);
                    split2(v10, v11, h1, l1);
                    const int pidx = dd >> 1;
                    const size_t o0 = ((size_t)(b0_*H_ + hh)*S_ + s0)*32 + pidx;
                    const size_t o1 = ((size_t)(b1_*H_ + hh)*S_ + s1)*32 + pidx;
                    Ch[o0] = h0;  Cl[o0] = l0;
                    Ch[o1] = h1;  Cl[o1] = l1;
                }
            }
        }
    }
}

// ======================================================================
// logits v4: pre-split Q/K inputs, cp.async. 128m x 256n strip.
// dyn smem (words): AH slab s @ s*2560, AL @ 5120+s*2560,
//   B stage st: BH @ 10240+st*2560, BL @ +1280.
// grid (8, 16, 24)
// ======================================================================
__global__ __launch_bounds__(256, 2)
void logits_ps(const unsigned* __restrict__ Qh, const unsigned* __restrict__ Ql,
               const unsigned* __restrict__ Kh, const unsigned* __restrict__ Kl,
               const int*   __restrict__ mask,
               float* __restrict__ attn,
               float* __restrict__ cmax,
               float* __restrict__ csum)
{
    extern __shared__ unsigned dsm[];
    __shared__ int   smask[256];
    __shared__ float smx[2][128], ssm[2][128];

    const int t = threadIdx.x, wid = t >> 5, lane = t & 31;
    const int gid = lane >> 2, tig = lane & 3;
    const int nbase = blockIdx.x * 256, m0 = blockIdx.y * 128;
    const int bh = blockIdx.z, b = bh / H_;
    const int wm = (wid & 3) * 32, wn = (wid >> 2) * 32;
    const int hf = wid >> 2;

    const int a_r = lane & 15, a_c = ((lane >> 4) & 1) * 4;
    const int b_r = (lane & 7) + ((lane >> 4) & 1) * 8;
    const int b_c = ((lane >> 3) & 1) * 4;

    smask[t] = mask[b * S_ + nbase + t];

    const int arow = t >> 1, aslab = t & 1;
    const int br2 = t >> 2, bg2 = t & 3;

    // ---- prologue: A (both slabs) + B it0 via cp.async, one group
    {
        const unsigned* QhP = Qh + ((size_t)bh * S_ + m0 + arow) * 32 + aslab * 16;
        const unsigned* QlP = Ql + ((size_t)bh * S_ + m0 + arow) * 32 + aslab * 16;
        unsigned* AH = dsm + aslab * 2560 + arow * 20;
        unsigned* AL = dsm + 5120 + aslab * 2560 + arow * 20;
#pragma unroll
        for (int q = 0; q < 4; q++) {
            cp16(AH + q*4, QhP + q*4);
            cp16(AL + q*4, QlP + q*4);
        }
        const unsigned* KhP = Kh + ((size_t)bh * S_ + nbase + br2) * 32 + bg2 * 4;
        const unsigned* KlP = Kl + ((size_t)bh * S_ + nbase + br2) * 32 + bg2 * 4;
        cp16(dsm + 10240        + br2*20 + bg2*4, KhP);
        cp16(dsm + 10240 + 1280 + br2*20 + bg2*4, KlP);
        CP_COMMIT();
    }

    float runm[2][2], runs[2][2];
#pragma unroll
    for (int i = 0; i < 2; i++)
#pragma unroll
        for (int j = 0; j < 2; j++) { runm[i][j] = neg_inf(); runs[i][j] = 0.0f; }

    float acc[2][4][4];
    float* Cb = attn + (size_t)bh * S_ * S_;

#pragma unroll
    for (int it = 0; it < 8; it++) {
        const int ni = it >> 1, ks = it & 1, st = it & 1;
        if (ks == 0) {
#pragma unroll
            for (int i = 0; i < 2; i++)
#pragma unroll
                for (int j = 0; j < 4; j++)
#pragma unroll
                    for (int q = 0; q < 4; q++) acc[i][j][q] = 0.0f;
        }

        CP_WAIT0();
        __syncthreads();

        if (it + 1 < 8) {
            const int niN = (it+1) >> 1, ksN = (it+1) & 1;
            const unsigned* KhP = Kh + ((size_t)bh * S_ + nbase + niN*64 + br2) * 32
                                  + ksN*16 + bg2*4;
            const unsigned* KlP = Kl + ((size_t)bh * S_ + nbase + niN*64 + br2) * 32
                                  + ksN*16 + bg2*4;
            cp16(dsm + 10240 + (st^1)*2560        + br2*20 + bg2*4, KhP);
            cp16(dsm + 10240 + (st^1)*2560 + 1280 + br2*20 + bg2*4, KlP);
            CP_COMMIT();
        }

        // ---- mma: A slab ks, B stage st
#pragma unroll
        for (int step = 0; step < 2; step++) {
            const int kc = step * 8;
            unsigned ah[2][4], al[2][4], bhf[2][4], blf[2][4];
#pragma unroll
            for (int mt = 0; mt < 2; mt++) {
                ldsm_x4(ah[mt], dsm + ks*2560        + (wm + mt*16 + a_r)*20 + kc + a_c);
                ldsm_x4(al[mt], dsm + 5120 + ks*2560 + (wm + mt*16 + a_r)*20 + kc + a_c);
            }
#pragma unroll
            for (int np = 0; np < 2; np++) {
                ldsm_x4(bhf[np], dsm + 10240 + st*2560        + (wn + np*16 + b_r)*20 + kc + b_c);
                ldsm_x4(blf[np], dsm + 10240 + st*2560 + 1280 + (wn + np*16 + b_r)*20 + kc + b_c);
            }
#pragma unroll
            for (int nt = 0; nt < 4; nt++) {
                const unsigned b0v = bhf[nt>>1][(nt&1)*2], b1v = bhf[nt>>1][(nt&1)*2+1];
                const unsigned c0v = blf[nt>>1][(nt&1)*2], c1v = blf[nt>>1][(nt&1)*2+1];
#pragma unroll
                for (int mt = 0; mt < 2; mt++) {
                    mma16(acc[mt][nt], ah[mt][0],ah[mt][1],ah[mt][2],ah[mt][3], b0v, b1v);
                    mma16(acc[mt][nt], ah[mt][0],ah[mt][1],ah[mt][2],ah[mt][3], c0v, c1v);
                    mma16(acc[mt][nt], al[mt][0],al[mt][1],al[mt][2],al[mt][3], b0v, b1v);
                }
            }
        }

        if (ks == 1) {
            bool mz[4][2];
#pragma unroll
            for (int nt = 0; nt < 4; nt++) {
                const int lc = ni*64 + wn + nt*8 + tig*2;
                mz[nt][0] = (smask[lc] == 0);
                mz[nt][1] = (smask[lc+1] == 0);
            }
#pragma unroll
            for (int mt = 0; mt < 2; mt++) {
#pragma unroll
                for (int nt = 0; nt < 4; nt++) {
                    const int r0 = m0 + wm + mt*16 + gid;
                    const int r1 = r0 + 8;
                    const int c  = nbase + ni*64 + wn + nt*8 + tig*2;
                    float2 v0, v1;
                    v0.x = mz[nt][0] ? neg_inf() : acc[mt][nt][0];
                    v0.y = mz[nt][1] ? neg_inf() : acc[mt][nt][1];
                    v1.x = mz[nt][0] ? neg_inf() : acc[mt][nt][2];
                    v1.y = mz[nt][1] ? neg_inf() : acc[mt][nt][3];
                    *(float2*)(Cb + (size_t)r0 * S_ + c) = v0;
                    *(float2*)(Cb + (size_t)r1 * S_ + c) = v1;
                }
            }
#pragma unroll
            for (int mt = 0; mt < 2; mt++) {
#pragma unroll
                for (int rh = 0; rh < 2; rh++) {
                    float mx = neg_inf();
#pragma unroll
                    for (int nt = 0; nt < 4; nt++) {
                        float v0 = mz[nt][0] ? neg_inf() : acc[mt][nt][rh*2];
                        float v1 = mz[nt][1] ? neg_inf() : acc[mt][nt][rh*2+1];
                        mx = fmaxf(mx, fmaxf(v0, v1));
                    }
                    mx = fmaxf(mx, __shfl_xor_sync(0xffffffffu, mx, 1));
                    mx = fmaxf(mx, __shfl_xor_sync(0xffffffffu, mx, 2));
                    float s = 0.0f;
                    if (mx != neg_inf()) {
#pragma unroll
                        for (int nt = 0; nt < 4; nt++) {
                            if (!mz[nt][0]) s += __expf(acc[mt][nt][rh*2]   - mx);
                            if (!mz[nt][1]) s += __expf(acc[mt][nt][rh*2+1] - mx);
                        }
                    }
                    s += __shfl_xor_sync(0xffffffffu, s, 1);
                    s += __shfl_xor_sync(0xffffffffu, s, 2);
                    if (mx > runm[mt][rh]) {
                        runs[mt][rh] = runs[mt][rh] * __expf(runm[mt][rh] - mx) + s;
                        runm[mt][rh] = mx;
                    } else if (mx != neg_inf()) {
                        runs[mt][rh] += s * __expf(mx - runm[mt][rh]);
                    }
                }
            }
        }
    }

    __syncthreads();
    if (tig == 0) {
#pragma unroll
        for (int mt = 0; mt < 2; mt++)
#pragma unroll
            for (int rh = 0; rh < 2; rh++) {
                const int row = wm + mt*16 + rh*8 + gid;
                smx[hf][row] = runm[mt][rh];
                ssm[hf][row] = runs[mt][rh];
            }
    }
    __syncthreads();
    if (t < 128) {
        const float m0v = smx[0][t], m1v = smx[1][t];
        const float s0 = ssm[0][t], s1 = ssm[1][t];
        const float M = fmaxf(m0v, m1v);
        float S = 0.0f;
        if (m0v != neg_inf()) S += s0 * __expf(m0v - M);
        if (m1v != neg_inf()) S += s1 * __expf(m1v - M);
        const size_t row = (size_t)bh * S_ + m0 + t;
        cmax[row * NCHUNK + blockIdx.x] = M;
        csum[row * NCHUNK + blockIdx.x] = S;
    }
}

// ======================================================================
__global__ __launch_bounds__(256)
void chunk_reduce(const float* __restrict__ cmax,
                  const float* __restrict__ csum,
                  float* __restrict__ gmax,
                  float* __restrict__ ginv)
{
    const int r = blockIdx.x * 256 + threadIdx.x;
    if (r >= BH_ * S_) return;
    float M = neg_inf(), S = 0.0f;
#pragma unroll
    for (int c = 0; c < NCHUNK; c++) {
        const float m = cmax[(size_t)r * NCHUNK + c];
        const float s = csum[(size_t)r * NCHUNK + c];
        if (m > M) { S = S * __expf(M - m) + s; M = m; }
        else if (m != neg_inf()) { S += s * __expf(m - M); }
    }
    gmax[r] = M;
    ginv[r] = 1.0f / S;
}

// ======================================================================
__global__ __launch_bounds__(256)
void vsplit_kernel(const float* __restrict__ Vp,
                   unsigned* __restrict__ Vth,
                   unsigned* __restrict__ Vtl)
{
    __shared__ float tile[32][65];
    const int t = threadIdx.x;
    const int n0 = blockIdx.x * 32;
    const int bh = blockIdx.y;

#pragma unroll
    for (int i = 0; i < 8; i++) {
        const int idx = t + i * 256;
        const int r = idx >> 6, c = idx & 63;
        tile[r][c] = Vp[((size_t)bh * S_ + n0 + r) * DEP_ + c];
    }
    __syncthreads();

#pragma unroll
    for (int i = 0; i < 4; i++) {
        const int idx = t * 4 + i;
        const int d = idx >> 4, np = idx & 15;
        unsigned h, l;
        split2(tile[2*np][d], tile[2*np + 1][d], h, l);
        const size_t o = ((size_t)bh * DEP_ + d) * (S_/2) + n0/2 + np;
        Vth[o] = h;
        Vtl[o] = l;
    }
}

// ======================================================================
// ctx v3: V via cp.async; A normalized+split in-kernel; pair outputs.
// dyn smem (words): A stage st @ st*5120 {AH +0, AL +2560};
//   V stage st @ 10240+st*2560 {VH, VL +1280}. grid (16, 24)
// ======================================================================
__global__ __launch_bounds__(256, 2)
void ctx_ps(float* __restrict__ attn,
            const unsigned* __restrict__ Vth,
            const unsigned* __restrict__ Vtl,
            const float* __restrict__ gmax,
            const float* __restrict__ ginv,
            unsigned* __restrict__ Ch, unsigned* __restrict__ Cl)
{
    extern __shared__ unsigned dsm[];

    const int t = threadIdx.x, wid = t >> 5, lane = t & 31;
    const int gid = lane >> 2, tig = lane & 3;
    const int m0 = blockIdx.x * 128;
    const int bh = blockIdx.y;
    const int b  = bh / H_, hh = bh % H_;
    const int wm = (wid & 3) * 32, wd = (wid >> 2) * 32;

    const int a_r = lane & 15, a_c = ((lane >> 4) & 1) * 4;
    const int b_r = (lane & 7) + ((lane >> 4) & 1) * 8;
    const int b_c = ((lane >> 3) & 1) * 4;

    const int lr = t >> 1, lg = t & 1;
    const int vr = t >> 2, vg = t & 3;

    float* Ap = attn + ((size_t)bh * S_ + m0 + lr) * S_ + lg * 16;
    const unsigned* VthB = Vth + ((size_t)bh * DEP_ + vr) * (S_/2) + vg * 4;
    const unsigned* VtlB = Vtl + ((size_t)bh * DEP_ + vr) * (S_/2) + vg * 4;

    const float mr = gmax[bh * S_ + m0 + lr];
    const float ir = ginv[bh * S_ + m0 + lr];

    float acc[2][4][4];
#pragma unroll
    for (int i = 0; i < 2; i++)
#pragma unroll
        for (int j = 0; j < 4; j++)
#pragma unroll
            for (int q = 0; q < 4; q++) acc[i][j][q] = 0.0f;

    float4 av[4];

    // ---- prologue: A0 process -> stage 0; V0 cp.async -> stage 0
#pragma unroll
    for (int j = 0; j < 4; j++) av[j] = *(const float4*)(Ap + j * 4);
    {
        unsigned* AH = dsm;  unsigned* AL = dsm + 2560;
#pragma unroll
        for (int j = 0; j < 4; j++) {
            float4 pv;
            pv.x = __expf(av[j].x - mr) * ir;
            pv.y = __expf(av[j].y - mr) * ir;
            pv.z = __expf(av[j].z - mr) * ir;
            pv.w = __expf(av[j].w - mr) * ir;
            *(float4*)(Ap + j * 4) = pv;
            unsigned h2, l2;
            split2(pv.x, pv.y, h2, l2);
            AH[lr*20 + lg*8 + 2*j]   = h2;  AL[lr*20 + lg*8 + 2*j]   = l2;
            split2(pv.z, pv.w, h2, l2);
            AH[lr*20 + lg*8 + 2*j+1] = h2;  AL[lr*20 + lg*8 + 2*j+1] = l2;
        }
        cp16(dsm + 10240        + vr*20 + vg*4, VthB);
        cp16(dsm + 10240 + 1280 + vr*20 + vg*4, VtlB);
        CP_COMMIT();
    }

#pragma unroll 1
    for (int i = 0; i < 64; i++) {
        const int st = i & 1;

        if (i + 1 < 64) {
            const int nc = (i + 1) * 32;
#pragma unroll
            for (int j = 0; j < 4; j++) av[j] = *(const float4*)(Ap + nc + j * 4);
        }

        CP_WAIT0();
        __syncthreads();

        if (i + 1 < 64) {
            const int nc = (i + 1) * 32;
            cp16(dsm + 10240 + (st^1)*2560        + vr*20 + vg*4, VthB + nc/2);
            cp16(dsm + 10240 + (st^1)*2560 + 1280 + vr*20 + vg*4, VtlB + nc/2);
            CP_COMMIT();
        }

        // ---- mma from stage st
#pragma unroll
        for (int step = 0; step < 2; step++) {
            const int kc = step * 8;
            unsigned ah[2][4], al[2][4], bhf[2][4], blf[2][4];
#pragma unroll
            for (int mt = 0; mt < 2; mt++) {
                ldsm_x4(ah[mt], dsm + st*5120        + (wm + mt*16 + a_r)*20 + kc + a_c);
                ldsm_x4(al[mt], dsm + st*5120 + 2560 + (wm + mt*16 + a_r)*20 + kc + a_c);
            }
#pragma unroll
            for (int np = 0; np < 2; np++) {
                ldsm_x4(bhf[np], dsm + 10240 + st*2560        + (wd + np*16 + b_r)*20 + kc + b_c);
                ldsm_x4(blf[np], dsm + 10240 + st*2560 + 1280 + (wd + np*16 + b_r)*20 + kc + b_c);
            }
#pragma unroll
            for (int dt = 0; dt < 4; dt++) {
                const unsigned bh0 = bhf[dt>>1][(dt&1)*2], bh1 = bhf[dt>>1][(dt&1)*2+1];
                const unsigned bl0 = blf[dt>>1][(dt&1)*2], bl1 = blf[dt>>1][(dt&1)*2+1];
#pragma unroll
                for (int mt = 0; mt < 2; mt++) {
                    mma16(acc[mt][dt], ah[mt][0],ah[mt][1],ah[mt][2],ah[mt][3], bh0, bh1);
                    mma16(acc[mt][dt], ah[mt][0],ah[mt][1],ah[mt][2],ah[mt][3], bl0, bl1);
                    mma16(acc[mt][dt], al[mt][0],al[mt][1],al[mt][2],al[mt][3], bh0, bh1);
                }
            }
        }

        // ---- process A slab i+1 -> stage st^1
        if (i + 1 < 64) {
            const int nc = (i + 1) * 32;
            unsigned* AH = dsm + (st^1)*5120;
            unsigned* AL = AH + 2560;
#pragma unroll
            for (int j = 0; j < 4; j++) {
                float4 pv;
                pv.x = __expf(av[j].x - mr) * ir;
                pv.y = __expf(av[j].y - mr) * ir;
                pv.z = __expf(av[j].z - mr) * ir;
                pv.w = __expf(av[j].w - mr) * ir;
                *(float4*)(Ap + nc + j * 4) = pv;
                unsigned h2, l2;
                split2(pv.x, pv.y, h2, l2);
                AH[lr*20 + lg*8 + 2*j]   = h2;  AL[lr*20 + lg*8 + 2*j]   = l2;
                split2(pv.z, pv.w, h2, l2);
                AH[lr*20 + lg*8 + 2*j+1] = h2;  AL[lr*20 + lg*8 + 2*j+1] = l2;
            }
        }
    }

    // epilogue: write ctx as split pairs (plain [M, 384] pair layout)
#pragma unroll
    for (int mt = 0; mt < 2; mt++) {
#pragma unroll
        for (int dt = 0; dt < 4; dt++) {
            const int r0 = m0 + wm + mt*16 + gid;
            const int r1 = r0 + 8;
            const int d  = wd + dt*8 + tig*2;
            unsigned h0, l0, h1, l1;
            split2(acc[mt][dt][0], acc[mt][dt][1], h0, l0);
            split2(acc[mt][dt][2], acc[mt][dt][3], h1, l1);
            const int pidx = hh*32 + (d >> 1);
            const size_t o0 = ((size_t)b * S_ + r0) * KP_ + pidx;
            const size_t o1 = ((size_t)b * S_ + r1) * KP_ + pidx;
            Ch[o0] = h0;  Cl[o0] = l0;
            Ch[o1] = h1;  Cl[o1] = l1;
        }
    }
}

// ======================================================================
extern "C" void kernel_launch(void* const* d_in, const int* in_sizes, int n_in,
                              void* d_out, int out_size)
{
    const float* q    = (const float*)d_in[0];
    const float* k    = (const float*)d_in[1];
    const float* v    = (const float*)d_in[2];
    const int*   mask = (const int*)  d_in[3];
    const float* wq_w = (const float*)d_in[4];
    const float* wq_b = (const float*)d_in[5];
    const float* wk_w = (const float*)d_in[6];
    const float* wk_b = (const float*)d_in[7];
    const float* wv_w = (const float*)d_in[8];
    const float* wv_b = (const float*)d_in[9];
    const float* wo_w = (const float*)d_in[10];
    const float* wo_b = (const float*)d_in[11];
    float* out = (float*)d_out;

    unsigned *Xh, *Xl, *Wh, *Wl, *Qph, *Qpl, *Kph, *Kpl, *Vth, *Vtl, *Ch, *Cl;
    float *Vp, *rmax, *rinv, *cmax, *csum, *attn_s;
    cudaGetSymbolAddress((void**)&Xh,  g_Xh);
    cudaGetSymbolAddress((void**)&Xl,  g_Xl);
    cudaGetSymbolAddress((void**)&Wh,  g_Wh);
    cudaGetSymbolAddress((void**)&Wl,  g_Wl);
    cudaGetSymbolAddress((void**)&Qph, g_Qph);
    cudaGetSymbolAddress((void**)&Qpl, g_Qpl);
    cudaGetSymbolAddress((void**)&Kph, g_Kph);
    cudaGetSymbolAddress((void**)&Kpl, g_Kpl);
    cudaGetSymbolAddress((void**)&Vp,  g_Vp);
    cudaGetSymbolAddress((void**)&Vth, g_Vth);
    cudaGetSymbolAddress((void**)&Vtl, g_Vtl);
    cudaGetSymbolAddress((void**)&Ch,  g_Ch);
    cudaGetSymbolAddress((void**)&Cl,  g_Cl);
    cudaGetSymbolAddress((void**)&rmax, g_rowmax);
    cudaGetSymbolAddress((void**)&rinv, g_rowinv);
    cudaGetSymbolAddress((void**)&cmax, g_cmax);
    cudaGetSymbolAddress((void**)&csum, g_csum);
    cudaGetSymbolAddress((void**)&attn_s, g_attn_scratch);

    const long long need = (long long)OUT_ELEMS + (long long)ATTN_ELEMS;
    float* attn = ((long long)out_size >= need) ? (out + OUT_ELEMS) : attn_s;

    cudaFuncSetAttribute(gemm_ps,
                         cudaFuncAttributeMaxDynamicSharedMemorySize, DYN_SMEM_BYTES);
    cudaFuncSetAttribute(logits_ps,
                         cudaFuncAttributeMaxDynamicSharedMemorySize, DYN_SMEM_BYTES);
    cudaFuncSetAttribute(ctx_ps,
                         cudaFuncAttributeMaxDynamicSharedMemorySize, DYN_SMEM_BYTES);

    const int XPAIRS = MROWS * KP_;       // 1572864
    const int WPAIRS = D_ * KP_;          // 294912
    dim3 pgrid(D_/64, MROWS/128);

    // Q projection (alpha = 1/8), pair output
    presplit<<<XPAIRS/1024, 256>>>(q, Xh, Xl, XPAIRS);
    presplit<<<WPAIRS/1024, 256>>>(wq_w, Wh, Wl, WPAIRS);
    gemm_ps<<<pgrid, 256, DYN_SMEM_BYTES>>>(Xh, Xl, Wh, Wl, wq_b,
                                            nullptr, Qph, Qpl, KP_, D_, 0.125f, 2);
    // K projection, pair output
    presplit<<<XPAIRS/1024, 256>>>(k, Xh, Xl, XPAIRS);
    presplit<<<WPAIRS/1024, 256>>>(wk_w, Wh, Wl, WPAIRS);
    gemm_ps<<<pgrid, 256, DYN_SMEM_BYTES>>>(Xh, Xl, Wh, Wl, wk_b,
                                            nullptr, Kph, Kpl, KP_, D_, 1.0f, 2);
    // V projection, fp32 head-split
    presplit<<<XPAIRS/1024, 256>>>(v, Xh, Xl, XPAIRS);
    presplit<<<WPAIRS/1024, 256>>>(wv_w, Wh, Wl, WPAIRS);
    gemm_ps<<<pgrid, 256, DYN_SMEM_BYTES>>>(Xh, Xl, Wh, Wl, wv_b,
                                            Vp, nullptr, nullptr, KP_, D_, 1.0f, 1);

    // V split/transpose for AV
    vsplit_kernel<<<dim3(S_/32, BH_), 256>>>(Vp, Vth, Vtl);

    // raw masked logits + softmax partials
    logits_ps<<<dim3(S_/256, S_/128, BH_), 256, DYN_SMEM_BYTES>>>(
        Qph, Qpl, Kph, Kpl, mask, attn, cmax, csum);

    // combine partials -> row stats
    chunk_reduce<<<dim3((BH_*S_ + 255)/256), 256>>>(cmax, csum, rmax, rinv);

    // ctx = softmax @ V (normalizes attn in place), pair output
    ctx_ps<<<dim3(S_/128, BH_), 256, DYN_SMEM_BYTES>>>(
        attn, Vth, Vtl, rmax, rinv, Ch, Cl);

    // output projection (fp32 out)
    presplit<<<WPAIRS/1024, 256>>>(wo_w, Wh, Wl, WPAIRS);
    gemm_ps<<<pgrid, 256, DYN_SMEM_BYTES>>>(Ch, Cl, Wh, Wl, wo_b,
                                            out, nullptr, nullptr, KP_, D_, 1.0f, 0);
}

// round 14
// speedup vs baseline: 1.4323x; 1.4323x over previous
#include <cuda_runtime.h>
#include <cuda_bf16.h>
#include <math.h>

#define B_    2
#define S_    2048
#define D_    768
#define H_    12
#define DEP_  64
#define BH_   (B_*H_)            // 24
#define MROWS (B_*S_)            // 4096
#define OUT_ELEMS (B_*S_*D_)     // 3145728
#define ATTN_ELEMS (BH_*S_*S_)   // 100663296
#define NCHUNK 8

#define DYN_SMEM_BYTES 61440     // 15360 words, all three mma kernels

// ---- scratch (alloc-free, __device__ globals) ----
__device__ float g_Qp[BH_*S_*DEP_];
__device__ float g_Kp[BH_*S_*DEP_];
__device__ float g_ctx[MROWS*D_];
__device__ float g_rowmax[BH_*S_];
__device__ float g_rowinv[BH_*S_];
__device__ float g_cmax[BH_*S_*NCHUNK];
__device__ float g_csum[BH_*S_*NCHUNK];
__device__ unsigned g_Vth[BH_*DEP_*(S_/2)];
__device__ unsigned g_Vtl[BH_*DEP_*(S_/2)];
__device__ float g_attn_scratch[ATTN_ELEMS];

__device__ __forceinline__ float neg_inf() { return __int_as_float(0xff800000); }

__device__ __forceinline__ void split2(float x, float y, unsigned& h, unsigned& l) {
    __nv_bfloat162 hv = __floats2bfloat162_rn(x, y);
    float2 hf = __bfloat1622float2(hv);
    __nv_bfloat162 lv = __floats2bfloat162_rn(x - hf.x, y - hf.y);
    h = *(unsigned*)&hv;
    l = *(unsigned*)&lv;
}

__device__ __forceinline__ void mma16(float* c,
                                      unsigned a0, unsigned a1, unsigned a2, unsigned a3,
                                      unsigned b0, unsigned b1) {
    asm volatile(
        "mma.sync.aligned.m16n8k16.row.col.f32.bf16.bf16.f32 "
        "{%0,%1,%2,%3}, {%4,%5,%6,%7}, {%8,%9}, {%0,%1,%2,%3};\n"
        : "+f"(c[0]), "+f"(c[1]), "+f"(c[2]), "+f"(c[3])
        : "r"(a0), "r"(a1), "r"(a2), "r"(a3), "r"(b0), "r"(b1));
}

__device__ __forceinline__ void ldsm_x4(unsigned* r, const void* p) {
    unsigned addr = (unsigned)__cvta_generic_to_shared(p);
    asm volatile("ldmatrix.sync.aligned.m8n8.x4.shared.b16 {%0,%1,%2,%3}, [%4];"
        : "=r"(r[0]), "=r"(r[1]), "=r"(r[2]), "=r"(r[3]) : "r"(addr));
}

// ======================================================================
// Projection GEMM (R12): C = alpha*(X @ W^T + bias); 128m x 64n tile,
// k-slab 32, double-buffered smem stages, ONE sync per slab.
// head_split: 0 = fp32 [M,N]; 1 = fp32 [B,H,S,DEP];
//             3 = V mode: split+transpose into Vth/Vtl [bh, d, npair]
// dyn smem layout (words), stage st in {0,1}, base = st*7680:
//   AH @ base, AL @ base+2560, BH @ base+5120, BL @ base+6400
// ======================================================================
__global__ __launch_bounds__(256, 2)
void gemm_xwT_bf16(const float* __restrict__ X,
                   const float* __restrict__ W,
                   const float* __restrict__ bias,
                   float* __restrict__ C,
                   unsigned* __restrict__ Vth,
                   unsigned* __restrict__ Vtl,
                   int K, int N, float alpha, int head_split)
{
    extern __shared__ unsigned dsm[];

    const int t = threadIdx.x, wid = t >> 5, lane = t & 31;
    const int gid = lane >> 2, tig = lane & 3;
    const int n0 = blockIdx.x * 64, m0 = blockIdx.y * 128;
    const int wm = (wid & 3) * 32, wn = (wid >> 2) * 32;

    const int a_r = lane & 15, a_c = ((lane >> 4) & 1) * 4;
    const int b_r = (lane & 7) + ((lane >> 4) & 1) * 8;
    const int b_c = ((lane >> 3) & 1) * 4;

    const int lr = t >> 1, lg = t & 1;   // A: row, half(16 floats)
    const int br = t >> 2, bg = t & 3;   // B: row, quarter(8 floats)

    const float* Xp = X + (size_t)(m0 + lr) * K + lg * 16;
    const float* Wp = W + (size_t)(n0 + br) * K + bg * 8;

    float acc[2][4][4];
#pragma unroll
    for (int i = 0; i < 2; i++)
#pragma unroll
        for (int j = 0; j < 4; j++)
#pragma unroll
            for (int q = 0; q < 4; q++) acc[i][j][q] = 0.0f;

    const int NS = K / 32;

    float4 xa[4], wb[2];
#pragma unroll
    for (int j = 0; j < 4; j++) xa[j] = *(const float4*)(Xp + j * 4);
#pragma unroll
    for (int j = 0; j < 2; j++) wb[j] = *(const float4*)(Wp + j * 4);

    // store slab 0 -> stage 0
    {
        unsigned* AH = dsm;            unsigned* AL = dsm + 2560;
        unsigned* BH = dsm + 5120;     unsigned* BL = dsm + 6400;
#pragma unroll
        for (int j = 0; j < 4; j++) {
            unsigned h, l;
            split2(xa[j].x, xa[j].y, h, l);
            AH[lr*20 + lg*8 + 2*j]   = h;  AL[lr*20 + lg*8 + 2*j]   = l;
            split2(xa[j].z, xa[j].w, h, l);
            AH[lr*20 + lg*8 + 2*j+1] = h;  AL[lr*20 + lg*8 + 2*j+1] = l;
        }
#pragma unroll
        for (int j = 0; j < 2; j++) {
            unsigned h, l;
            split2(wb[j].x, wb[j].y, h, l);
            BH[br*20 + bg*4 + 2*j]   = h;  BL[br*20 + bg*4 + 2*j]   = l;
            split2(wb[j].z, wb[j].w, h, l);
            BH[br*20 + bg*4 + 2*j+1] = h;  BL[br*20 + bg*4 + 2*j+1] = l;
        }
    }
    __syncthreads();

#pragma unroll 1
    for (int s = 0; s < NS; s++) {
        const int st = s & 1;
        const unsigned base = st * 7680;

        if (s + 1 < NS) {
            const int k0 = (s + 1) * 32;
#pragma unroll
            for (int j = 0; j < 4; j++) xa[j] = *(const float4*)(Xp + k0 + j * 4);
#pragma unroll
            for (int j = 0; j < 2; j++) wb[j] = *(const float4*)(Wp + k0 + j * 4);
        }

        // mma from stage st
#pragma unroll
        for (int step = 0; step < 2; step++) {
            const int kc = step * 8;
            unsigned ah[2][4], al[2][4], bhf[2][4], blf[2][4];
#pragma unroll
            for (int mt = 0; mt < 2; mt++) {
                ldsm_x4(ah[mt], dsm + base + (wm + mt*16 + a_r)*20 + kc + a_c);
                ldsm_x4(al[mt], dsm + base + 2560 + (wm + mt*16 + a_r)*20 + kc + a_c);
            }
#pragma unroll
            for (int np = 0; np < 2; np++) {
                ldsm_x4(bhf[np], dsm + base + 5120 + (wn + np*16 + b_r)*20 + kc + b_c);
                ldsm_x4(blf[np], dsm + base + 6400 + (wn + np*16 + b_r)*20 + kc + b_c);
            }
#pragma unroll
            for (int nt = 0; nt < 4; nt++) {
                const unsigned bh0 = bhf[nt>>1][(nt&1)*2], bh1 = bhf[nt>>1][(nt&1)*2+1];
                const unsigned bl0 = blf[nt>>1][(nt&1)*2], bl1 = blf[nt>>1][(nt&1)*2+1];
#pragma unroll
                for (int mt = 0; mt < 2; mt++) {
                    mma16(acc[mt][nt], ah[mt][0],ah[mt][1],ah[mt][2],ah[mt][3], bh0, bh1);
                    mma16(acc[mt][nt], ah[mt][0],ah[mt][1],ah[mt][2],ah[mt][3], bl0, bl1);
                    mma16(acc[mt][nt], al[mt][0],al[mt][1],al[mt][2],al[mt][3], bh0, bh1);
                }
            }
        }

        // store slab s+1 -> stage st^1
        if (s + 1 < NS) {
            const unsigned nb = (st ^ 1) * 7680;
            unsigned* AH = dsm + nb;          unsigned* AL = dsm + nb + 2560;
            unsigned* BH = dsm + nb + 5120;   unsigned* BL = dsm + nb + 6400;
#pragma unroll
            for (int j = 0; j < 4; j++) {
                unsigned h, l;
                split2(xa[j].x, xa[j].y, h, l);
                AH[lr*20 + lg*8 + 2*j]   = h;  AL[lr*20 + lg*8 + 2*j]   = l;
                split2(xa[j].z, xa[j].w, h, l);
                AH[lr*20 + lg*8 + 2*j+1] = h;  AL[lr*20 + lg*8 + 2*j+1] = l;
            }
#pragma unroll
            for (int j = 0; j < 2; j++) {
                unsigned h, l;
                split2(wb[j].x, wb[j].y, h, l);
                BH[br*20 + bg*4 + 2*j]   = h;  BL[br*20 + bg*4 + 2*j]   = l;
                split2(wb[j].z, wb[j].w, h, l);
                BH[br*20 + bg*4 + 2*j+1] = h;  BL[br*20 + bg*4 + 2*j+1] = l;
            }
        }
        __syncthreads();
    }

    if (head_split == 3) {
        // ---- V mode: stage fp32 tile in smem, then split+transpose out
        float* tf = (float*)dsm;   // [128][65] fp32 tile
#pragma unroll
        for (int mt = 0; mt < 2; mt++) {
#pragma unroll
            for (int nt = 0; nt < 4; nt++) {
                const int rl0 = wm + mt*16 + gid;
                const int rl1 = rl0 + 8;
                const int cl  = wn + nt*8 + tig*2;
                const float b0v = bias[n0 + cl], b1v = bias[n0 + cl + 1];
                tf[rl0*65 + cl]     = acc[mt][nt][0] + b0v;
                tf[rl0*65 + cl + 1] = acc[mt][nt][1] + b1v;
                tf[rl1*65 + cl]     = acc[mt][nt][2] + b0v;
                tf[rl1*65 + cl + 1] = acc[mt][nt][3] + b1v;
            }
        }
        __syncthreads();
        const int bb = m0 / S_, hh = n0 / DEP_;
        const int bh = bb * H_ + hh;
        const int p0 = (m0 % S_) / 2;
#pragma unroll
        for (int i = 0; i < 16; i++) {
            const int idx = t + i * 256;
            const int p = idx & 63;       // sequence pair within tile
            const int d = idx >> 6;       // 0..63
            unsigned h2, l2;
            split2(tf[(2*p)*65 + d], tf[(2*p + 1)*65 + d], h2, l2);
            const size_t o = ((size_t)bh * DEP_ + d) * (S_/2) + p0 + p;
            Vth[o] = h2;
            Vtl[o] = l2;
        }
        return;
    }

#pragma unroll
    for (int mt = 0; mt < 2; mt++) {
#pragma unroll
        for (int nt = 0; nt < 4; nt++) {
            const int r0 = m0 + wm + mt*16 + gid;
            const int r1 = r0 + 8;
            const int c  = n0 + wn + nt*8 + tig*2;
            const float b0v = bias[c], b1v = bias[c+1];
            float2 v0, v1;
            v0.x = alpha * (acc[mt][nt][0] + b0v);
            v0.y = alpha * (acc[mt][nt][1] + b1v);
            v1.x = alpha * (acc[mt][nt][2] + b0v);
            v1.y = alpha * (acc[mt][nt][3] + b1v);
            if (head_split == 1) {
                const int h = n0 / DEP_;
                const int dd = c - n0;
                const int b0_ = r0 / S_, s0 = r0 % S_;
                const int b1_ = r1 / S_, s1 = r1 % S_;
                *(float2*)(C + (((size_t)(b0_*H_ + h))*S_ + s0)*DEP_ + dd) = v0;
                *(float2*)(C + (((size_t)(b1_*H_ + h))*S_ + s1)*DEP_ + dd) = v1;
            } else {
                *(float2*)(C + (size_t)r0 * N + c) = v0;
                *(float2*)(C + (size_t)r1 * N + c) = v1;
            }
        }
    }
}

// ======================================================================
// logits v3 (R12): 128m x 256n strip; A(Q) smem-resident (both k-slabs),
// B double-buffered, ONE sync per iteration; fused online stats.
// dyn smem (words): AH slab s @ s*2560, AL @ 5120 + s*2560,
//   B stage st: BH @ 10240 + st*2560, BL @ +1280. grid (8, 16, 24)
// ======================================================================
__global__ __launch_bounds__(256, 2)
void logits_bf16(const float* __restrict__ Qp,
                 const float* __restrict__ Kp,
                 const int*   __restrict__ mask,
                 float* __restrict__ attn,
                 float* __restrict__ cmax,
                 float* __restrict__ csum)
{
    extern __shared__ unsigned dsm[];
    __shared__ int   smask[256];
    __shared__ float smx[2][128], ssm[2][128];

    const int t = threadIdx.x, wid = t >> 5, lane = t & 31;
    const int gid = lane >> 2, tig = lane & 3;
    const int nbase = blockIdx.x * 256, m0 = blockIdx.y * 128;
    const int bh = blockIdx.z, b = bh / H_;
    const int wm = (wid & 3) * 32, wn = (wid >> 2) * 32;
    const int hf = wid >> 2;

    const int a_r = lane & 15, a_c = ((lane >> 4) & 1) * 4;
    const int b_r = (lane & 7) + ((lane >> 4) & 1) * 8;
    const int b_c = ((lane >> 3) & 1) * 4;

    smask[t] = mask[b * S_ + nbase + t];

    const int br = t >> 2, bg = t & 3;

    // ---- A: load full K=64 into smem (slab = t&1, row = t>>1)
    {
        const int slab = t & 1, row = t >> 1;
        const float* Qb = Qp + ((size_t)bh * S_ + m0 + row) * DEP_ + slab * 32;
        unsigned* AH = dsm + slab * 2560;
        unsigned* AL = dsm + 5120 + slab * 2560;
#pragma unroll
        for (int g = 0; g < 4; g++) {
            float4 f0 = *(const float4*)(Qb + g * 8);
            float4 f1 = *(const float4*)(Qb + g * 8 + 4);
            unsigned h, l;
            split2(f0.x, f0.y, h, l);
            AH[row*20 + g*4 + 0] = h;  AL[row*20 + g*4 + 0] = l;
            split2(f0.z, f0.w, h, l);
            AH[row*20 + g*4 + 1] = h;  AL[row*20 + g*4 + 1] = l;
            split2(f1.x, f1.y, h, l);
            AH[row*20 + g*4 + 2] = h;  AL[row*20 + g*4 + 2] = l;
            split2(f1.z, f1.w, h, l);
            AH[row*20 + g*4 + 3] = h;  AL[row*20 + g*4 + 3] = l;
        }
    }

    // ---- B it=0 load + store into stage 0
    float4 wb[2];
    {
        const float* Kb = Kp + ((size_t)bh * S_ + nbase + br) * DEP_ + bg * 8;
#pragma unroll
        for (int j = 0; j < 2; j++) wb[j] = *(const float4*)(Kb + j * 4);
        unsigned* BH = dsm + 10240;
        unsigned* BL = dsm + 10240 + 1280;
#pragma unroll
        for (int j = 0; j < 2; j++) {
            unsigned h, l;
            split2(wb[j].x, wb[j].y, h, l);
            BH[br*20 + bg*4 + 2*j]   = h;  BL[br*20 + bg*4 + 2*j]   = l;
            split2(wb[j].z, wb[j].w, h, l);
            BH[br*20 + bg*4 + 2*j+1] = h;  BL[br*20 + bg*4 + 2*j+1] = l;
        }
    }
    __syncthreads();

    float runm[2][2], runs[2][2];
#pragma unroll
    for (int i = 0; i < 2; i++)
#pragma unroll
        for (int j = 0; j < 2; j++) { runm[i][j] = neg_inf(); runs[i][j] = 0.0f; }

    float acc[2][4][4];
    float* Cb = attn + (size_t)bh * S_ * S_;

#pragma unroll
    for (int it = 0; it < 8; it++) {
        const int ni = it >> 1, ks = it & 1, st = it & 1;
        if (ks == 0) {
#pragma unroll
            for (int i = 0; i < 2; i++)
#pragma unroll
                for (int j = 0; j < 4; j++)
#pragma unroll
                    for (int q = 0; q < 4; q++) acc[i][j][q] = 0.0f;
        }

        if (it + 1 < 8) {
            const int niN = (it+1) >> 1, ksN = (it+1) & 1;
            const float* Kb = Kp + ((size_t)bh * S_ + nbase + niN*64 + br) * DEP_
                              + ksN*32 + bg*8;
#pragma unroll
            for (int j = 0; j < 2; j++) wb[j] = *(const float4*)(Kb + j * 4);
        }

        // ---- mma: A slab ks, B stage st
#pragma unroll
        for (int step = 0; step < 2; step++) {
            const int kc = step * 8;
            unsigned ah[2][4], al[2][4], bhf[2][4], blf[2][4];
#pragma unroll
            for (int mt = 0; mt < 2; mt++) {
                ldsm_x4(ah[mt], dsm + ks*2560        + (wm + mt*16 + a_r)*20 + kc + a_c);
                ldsm_x4(al[mt], dsm + 5120 + ks*2560 + (wm + mt*16 + a_r)*20 + kc + a_c);
            }
#pragma unroll
            for (int np = 0; np < 2; np++) {
                ldsm_x4(bhf[np], dsm + 10240 + st*2560        + (wn + np*16 + b_r)*20 + kc + b_c);
                ldsm_x4(blf[np], dsm + 10240 + st*2560 + 1280 + (wn + np*16 + b_r)*20 + kc + b_c);
            }
#pragma unroll
            for (int nt = 0; nt < 4; nt++) {
                const unsigned b0v = bhf[nt>>1][(nt&1)*2], b1v = bhf[nt>>1][(nt&1)*2+1];
                const unsigned c0v = blf[nt>>1][(nt&1)*2], c1v = blf[nt>>1][(nt&1)*2+1];
#pragma unroll
                for (int mt = 0; mt < 2; mt++) {
                    mma16(acc[mt][nt], ah[mt][0],ah[mt][1],ah[mt][2],ah[mt][3], b0v, b1v);
                    mma16(acc[mt][nt], ah[mt][0],ah[mt][1],ah[mt][2],ah[mt][3], c0v, c1v);
                    mma16(acc[mt][nt], al[mt][0],al[mt][1],al[mt][2],al[mt][3], b0v, b1v);
                }
            }
        }

        if (ks == 1) {
            bool mz[4][2];
#pragma unroll
            for (int nt = 0; nt < 4; nt++) {
                const int lc = ni*64 + wn + nt*8 + tig*2;
                mz[nt][0] = (smask[lc] == 0);
                mz[nt][1] = (smask[lc+1] == 0);
            }
#pragma unroll
            for (int mt = 0; mt < 2; mt++) {
#pragma unroll
                for (int nt = 0; nt < 4; nt++) {
                    const int r0 = m0 + wm + mt*16 + gid;
                    const int r1 = r0 + 8;
                    const int c  = nbase + ni*64 + wn + nt*8 + tig*2;
                    float2 v0, v1;
                    v0.x = mz[nt][0] ? neg_inf() : acc[mt][nt][0];
                    v0.y = mz[nt][1] ? neg_inf() : acc[mt][nt][1];
                    v1.x = mz[nt][0] ? neg_inf() : acc[mt][nt][2];
                    v1.y = mz[nt][1] ? neg_inf() : acc[mt][nt][3];
                    *(float2*)(Cb + (size_t)r0 * S_ + c) = v0;
                    *(float2*)(Cb + (size_t)r1 * S_ + c) = v1;
                }
            }
#pragma unroll
            for (int mt = 0; mt < 2; mt++) {
#pragma unroll
                for (int rh = 0; rh < 2; rh++) {
                    float mx = neg_inf();
#pragma unroll
                    for (int nt = 0; nt < 4; nt++) {
                        float v0 = mz[nt][0] ? neg_inf() : acc[mt][nt][rh*2];
                        float v1 = mz[nt][1] ? neg_inf() : acc[mt][nt][rh*2+1];
                        mx = fmaxf(mx, fmaxf(v0, v1));
                    }
                    mx = fmaxf(mx, __shfl_xor_sync(0xffffffffu, mx, 1));
                    mx = fmaxf(mx, __shfl_xor_sync(0xffffffffu, mx, 2));
                    float s = 0.0f;
                    if (mx != neg_inf()) {
#pragma unroll
                        for (int nt = 0; nt < 4; nt++) {
                            if (!mz[nt][0]) s += __expf(acc[mt][nt][rh*2]   - mx);
                            if (!mz[nt][1]) s += __expf(acc[mt][nt][rh*2+1] - mx);
                        }
                    }
                    s += __shfl_xor_sync(0xffffffffu, s, 1);
                    s += __shfl_xor_sync(0xffffffffu, s, 2);
                    if (mx > runm[mt][rh]) {
                        runs[mt][rh] = runs[mt][rh] * __expf(runm[mt][rh] - mx) + s;
                        runm[mt][rh] = mx;
                    } else if (mx != neg_inf()) {
                        runs[mt][rh] += s * __expf(mx - runm[mt][rh]);
                    }
                }
            }
        }

        // ---- store B it+1 into stage st^1
        if (it + 1 < 8) {
            unsigned* BH = dsm + 10240 + (st^1)*2560;
            unsigned* BL = BH + 1280;
#pragma unroll
            for (int j = 0; j < 2; j++) {
                unsigned h, l;
                split2(wb[j].x, wb[j].y, h, l);
                BH[br*20 + bg*4 + 2*j]   = h;  BL[br*20 + bg*4 + 2*j]   = l;
                split2(wb[j].z, wb[j].w, h, l);
                BH[br*20 + bg*4 + 2*j+1] = h;  BL[br*20 + bg*4 + 2*j+1] = l;
            }
        }
        __syncthreads();
    }

    // ---- cross-half combine + write chunk partials
    if (tig == 0) {
#pragma unroll
        for (int mt = 0; mt < 2; mt++)
#pragma unroll
            for (int rh = 0; rh < 2; rh++) {
                const int row = wm + mt*16 + rh*8 + gid;
                smx[hf][row] = runm[mt][rh];
                ssm[hf][row] = runs[mt][rh];
            }
    }
    __syncthreads();
    if (t < 128) {
        const float m0v = smx[0][t], m1v = smx[1][t];
        const float s0 = ssm[0][t], s1 = ssm[1][t];
        const float M = fmaxf(m0v, m1v);
        float S = 0.0f;
        if (m0v != neg_inf()) S += s0 * __expf(m0v - M);
        if (m1v != neg_inf()) S += s1 * __expf(m1v - M);
        const size_t row = (size_t)bh * S_ + m0 + t;
        cmax[row * NCHUNK + blockIdx.x] = M;
        csum[row * NCHUNK + blockIdx.x] = S;
    }
}

// ======================================================================
__global__ __launch_bounds__(256)
void chunk_reduce(const float* __restrict__ cmax,
                  const float* __restrict__ csum,
                  float* __restrict__ gmax,
                  float* __restrict__ ginv)
{
    const int r = blockIdx.x * 256 + threadIdx.x;
    if (r >= BH_ * S_) return;
    float M = neg_inf(), S = 0.0f;
#pragma unroll
    for (int c = 0; c < NCHUNK; c++) {
        const float m = cmax[(size_t)r * NCHUNK + c];
        const float s = csum[(size_t)r * NCHUNK + c];
        if (m > M) { S = S * __expf(M - m) + s; M = m; }
        else if (m != neg_inf()) { S += s * __expf(m - M); }
    }
    gmax[r] = M;
    ginv[r] = 1.0f / S;
}

// ======================================================================
// ctx v2 (R12): double-buffered A and V stages, ONE sync per 32-n slab.
// dyn smem (words): A stage st: AH @ st*5120, AL @ st*5120+2560;
//   V stage st: VH @ 10240 + st*2560, VL @ +1280. grid (16, 24)
// ======================================================================
__global__ __launch_bounds__(256, 2)
void ctx_bf16(float* __restrict__ attn,
              const unsigned* __restrict__ Vth,
              const unsigned* __restrict__ Vtl,
              const float* __restrict__ gmax,
              const float* __restrict__ ginv,
              float* __restrict__ ctx)
{
    extern __shared__ unsigned dsm[];

    const int t = threadIdx.x, wid = t >> 5, lane = t & 31;
    const int gid = lane >> 2, tig = lane & 3;
    const int m0 = blockIdx.x * 128;
    const int bh = blockIdx.y;
    const int b  = bh / H_, h = bh % H_;
    const int wm = (wid & 3) * 32, wd = (wid >> 2) * 32;

    const int a_r = lane & 15, a_c = ((lane >> 4) & 1) * 4;
    const int b_r = (lane & 7) + ((lane >> 4) & 1) * 8;
    const int b_c = ((lane >> 3) & 1) * 4;

    const int lr = t >> 1, lg = t & 1;
    const int vr = t >> 2, vg = t & 3;

    float* Ap = attn + ((size_t)bh * S_ + m0 + lr) * S_ + lg * 16;
    const unsigned* VthB = Vth + ((size_t)bh * DEP_ + vr) * (S_/2) + vg * 4;
    const unsigned* VtlB = Vtl + ((size_t)bh * DEP_ + vr) * (S_/2) + vg * 4;

    const float mr = gmax[bh * S_ + m0 + lr];
    const float ir = ginv[bh * S_ + m0 + lr];

    float acc[2][4][4];
#pragma unroll
    for (int i = 0; i < 2; i++)
#pragma unroll
        for (int j = 0; j < 4; j++)
#pragma unroll
            for (int q = 0; q < 4; q++) acc[i][j][q] = 0.0f;

    float4 av[4];
    uint4 vh4, vl4;

    // ---- prologue: slab 0 -> stage 0
#pragma unroll
    for (int j = 0; j < 4; j++) av[j] = *(const float4*)(Ap + j * 4);
    vh4 = *(const uint4*)(VthB);
    vl4 = *(const uint4*)(VtlB);
    {
        unsigned* AH = dsm;          unsigned* AL = dsm + 2560;
        unsigned* VH = dsm + 10240;  unsigned* VL = dsm + 10240 + 1280;
#pragma unroll
        for (int j = 0; j < 4; j++) {
            float4 pv;
            pv.x = __expf(av[j].x - mr) * ir;
            pv.y = __expf(av[j].y - mr) * ir;
            pv.z = __expf(av[j].z - mr) * ir;
            pv.w = __expf(av[j].w - mr) * ir;
            *(float4*)(Ap + j * 4) = pv;
            unsigned hh, ll;
            split2(pv.x, pv.y, hh, ll);
            AH[lr*20 + lg*8 + 2*j]   = hh;  AL[lr*20 + lg*8 + 2*j]   = ll;
            split2(pv.z, pv.w, hh, ll);
            AH[lr*20 + lg*8 + 2*j+1] = hh;  AL[lr*20 + lg*8 + 2*j+1] = ll;
        }
        *(uint4*)&VH[vr*20 + vg*4] = vh4;
        *(uint4*)&VL[vr*20 + vg*4] = vl4;
    }
    __syncthreads();

#pragma unroll 1
    for (int i = 0; i < 64; i++) {
        const int st = i & 1;

        if (i + 1 < 64) {
            const int nc = (i + 1) * 32;
#pragma unroll
            for (int j = 0; j < 4; j++) av[j] = *(const float4*)(Ap + nc + j * 4);
            vh4 = *(const uint4*)(VthB + nc/2);
            vl4 = *(const uint4*)(VtlB + nc/2);
        }

        // ---- mma from stage st
#pragma unroll
        for (int step = 0; step < 2; step++) {
            const int kc = step * 8;
            unsigned ah[2][4], al[2][4], bhf[2][4], blf[2][4];
#pragma unroll
            for (int mt = 0; mt < 2; mt++) {
                ldsm_x4(ah[mt], dsm + st*5120        + (wm + mt*16 + a_r)*20 + kc + a_c);
                ldsm_x4(al[mt], dsm + st*5120 + 2560 + (wm + mt*16 + a_r)*20 + kc + a_c);
            }
#pragma unroll
            for (int np = 0; np < 2; np++) {
                ldsm_x4(bhf[np], dsm + 10240 + st*2560        + (wd + np*16 + b_r)*20 + kc + b_c);
                ldsm_x4(blf[np], dsm + 10240 + st*2560 + 1280 + (wd + np*16 + b_r)*20 + kc + b_c);
            }
#pragma unroll
            for (int dt = 0; dt < 4; dt++) {
                const unsigned bh0 = bhf[dt>>1][(dt&1)*2], bh1 = bhf[dt>>1][(dt&1)*2+1];
                const unsigned bl0 = blf[dt>>1][(dt&1)*2], bl1 = blf[dt>>1][(dt&1)*2+1];
#pragma unroll
                for (int mt = 0; mt < 2; mt++) {
                    mma16(acc[mt][dt], ah[mt][0],ah[mt][1],ah[mt][2],ah[mt][3], bh0, bh1);
                    mma16(acc[mt][dt], ah[mt][0],ah[mt][1],ah[mt][2],ah[mt][3], bl0, bl1);
                    mma16(acc[mt][dt], al[mt][0],al[mt][1],al[mt][2],al[mt][3], bh0, bh1);
                }
            }
        }

        // ---- process slab i+1 -> stage st^1
        if (i + 1 < 64) {
            const int nc = (i + 1) * 32;
            const unsigned ab = (st ^ 1) * 5120;
            unsigned* AH = dsm + ab;            unsigned* AL = dsm + ab + 2560;
            unsigned* VH = dsm + 10240 + (st^1)*2560;
            unsigned* VL = VH + 1280;
#pragma unroll
            for (int j = 0; j < 4; j++) {
                float4 pv;
                pv.x = __expf(av[j].x - mr) * ir;
                pv.y = __expf(av[j].y - mr) * ir;
                pv.z = __expf(av[j].z - mr) * ir;
                pv.w = __expf(av[j].w - mr) * ir;
                *(float4*)(Ap + nc + j * 4) = pv;
                unsigned hh, ll;
                split2(pv.x, pv.y, hh, ll);
                AH[lr*20 + lg*8 + 2*j]   = hh;  AL[lr*20 + lg*8 + 2*j]   = ll;
                split2(pv.z, pv.w, hh, ll);
                AH[lr*20 + lg*8 + 2*j+1] = hh;  AL[lr*20 + lg*8 + 2*j+1] = ll;
            }
            *(uint4*)&VH[vr*20 + vg*4] = vh4;
            *(uint4*)&VL[vr*20 + vg*4] = vl4;
        }
        __syncthreads();
    }

#pragma unroll
    for (int mt = 0; mt < 2; mt++) {
#pragma unroll
        for (int dt = 0; dt < 4; dt++) {
            const int r0 = m0 + wm + mt*16 + gid;
            const int r1 = r0 + 8;
            const int d  = wd + dt*8 + tig*2;
            float2 v0 = {acc[mt][dt][0], acc[mt][dt][1]};
            float2 v1 = {acc[mt][dt][2], acc[mt][dt][3]};
            *(float2*)(ctx + ((size_t)b * S_ + r0) * D_ + h * DEP_ + d) = v0;
            *(float2*)(ctx + ((size_t)b * S_ + r1) * D_ + h * DEP_ + d) = v1;
        }
    }
}

// ======================================================================
extern "C" void kernel_launch(void* const* d_in, const int* in_sizes, int n_in,
                              void* d_out, int out_size)
{
    const float* q    = (const float*)d_in[0];
    const float* k    = (const float*)d_in[1];
    const float* v    = (const float*)d_in[2];
    const int*   mask = (const int*)  d_in[3];
    const float* wq_w = (const float*)d_in[4];
    const float* wq_b = (const float*)d_in[5];
    const float* wk_w = (const float*)d_in[6];
    const float* wk_b = (const float*)d_in[7];
    const float* wv_w = (const float*)d_in[8];
    const float* wv_b = (const float*)d_in[9];
    const float* wo_w = (const float*)d_in[10];
    const float* wo_b = (const float*)d_in[11];
    float* out = (float*)d_out;

    float *Qp, *Kp, *ctxp, *rmax, *rinv, *cmax, *csum, *attn_s;
    unsigned *Vth, *Vtl;
    cudaGetSymbolAddress((void**)&Qp,     g_Qp);
    cudaGetSymbolAddress((void**)&Kp,     g_Kp);
    cudaGetSymbolAddress((void**)&ctxp,   g_ctx);
    cudaGetSymbolAddress((void**)&rmax,   g_rowmax);
    cudaGetSymbolAddress((void**)&rinv,   g_rowinv);
    cudaGetSymbolAddress((void**)&cmax,   g_cmax);
    cudaGetSymbolAddress((void**)&csum,   g_csum);
    cudaGetSymbolAddress((void**)&Vth,    g_Vth);
    cudaGetSymbolAddress((void**)&Vtl,    g_Vtl);
    cudaGetSymbolAddress((void**)&attn_s, g_attn_scratch);

    const long long need = (long long)OUT_ELEMS + (long long)ATTN_ELEMS;
    float* attn = ((long long)out_size >= need) ? (out + OUT_ELEMS) : attn_s;

    cudaFuncSetAttribute(gemm_xwT_bf16,
                         cudaFuncAttributeMaxDynamicSharedMemorySize, DYN_SMEM_BYTES);
    cudaFuncSetAttribute(logits_bf16,
                         cudaFuncAttributeMaxDynamicSharedMemorySize, DYN_SMEM_BYTES);
    cudaFuncSetAttribute(ctx_bf16,
                         cudaFuncAttributeMaxDynamicSharedMemorySize, DYN_SMEM_BYTES);

    // Q/K/V projections (Q pre-scaled by 1/8); V projection writes split
    // transposed Vth/Vtl directly (mode 3).
    dim3 pgrid(D_/64, MROWS/128);
    gemm_xwT_bf16<<<pgrid, 256, DYN_SMEM_BYTES>>>(q, wq_w, wq_b, Qp,
                                                  nullptr, nullptr,
                                                  D_, D_, 0.125f, 1);
    gemm_xwT_bf16<<<pgrid, 256, DYN_SMEM_BYTES>>>(k, wk_w, wk_b, Kp,
                                                  nullptr, nullptr,
                                                  D_, D_, 1.0f, 1);
    gemm_xwT_bf16<<<pgrid, 256, DYN_SMEM_BYTES>>>(v, wv_w, wv_b, nullptr,
                                                  Vth, Vtl,
                                                  D_, D_, 1.0f, 3);

    // raw masked logits + per-chunk softmax partials
    logits_bf16<<<dim3(S_/256, S_/128, BH_), 256, DYN_SMEM_BYTES>>>(
        Qp, Kp, mask, attn, cmax, csum);

    // combine partials -> row stats
    chunk_reduce<<<dim3((BH_*S_ + 255)/256), 256>>>(cmax, csum, rmax, rinv);

    // ctx = softmax @ V; normalizes attn in place
    ctx_bf16<<<dim3(S_/128, BH_), 256, DYN_SMEM_BYTES>>>(
        attn, Vth, Vtl, rmax, rinv, ctxp);

    // output projection
    gemm_xwT_bf16<<<pgrid, 256, DYN_SMEM_BYTES>>>(ctxp, wo_w, wo_b, out,
                                                  nullptr, nullptr,
                                                  D_, D_, 1.0f, 0);
}

// round 15
// speedup vs baseline: 1.4384x; 1.0042x over previous
#include <cuda_runtime.h>
#include <cuda_bf16.h>
#include <math.h>

#define B_    2
#define S_    2048
#define D_    768
#define H_    12
#define DEP_  64
#define BH_   (B_*H_)            // 24
#define MROWS (B_*S_)            // 4096
#define OUT_ELEMS (B_*S_*D_)     // 3145728
#define ATTN_ELEMS (BH_*S_*S_)   // 100663296
#define NCHUNK 8

#define DYN_SMEM_BYTES 61440     // 15360 words, all three mma kernels

// ---- scratch (alloc-free, __device__ globals) ----
__device__ float g_Qp[BH_*S_*DEP_];
__device__ float g_Kp[BH_*S_*DEP_];
__device__ float g_ctx[MROWS*D_];
__device__ float g_rowmax[BH_*S_];
__device__ float g_rowinv[BH_*S_];
__device__ float g_cmax[BH_*S_*NCHUNK];
__device__ float g_csum[BH_*S_*NCHUNK];
__device__ unsigned g_Vth[BH_*DEP_*(S_/2)];
__device__ unsigned g_Vtl[BH_*DEP_*(S_/2)];
__device__ float g_attn_scratch[ATTN_ELEMS];

__device__ __forceinline__ float neg_inf() { return __int_as_float(0xff800000); }

__device__ __forceinline__ void split2(float x, float y, unsigned& h, unsigned& l) {
    __nv_bfloat162 hv = __floats2bfloat162_rn(x, y);
    float2 hf = __bfloat1622float2(hv);
    __nv_bfloat162 lv = __floats2bfloat162_rn(x - hf.x, y - hf.y);
    h = *(unsigned*)&hv;
    l = *(unsigned*)&lv;
}

__device__ __forceinline__ void mma16(float* c,
                                      unsigned a0, unsigned a1, unsigned a2, unsigned a3,
                                      unsigned b0, unsigned b1) {
    asm volatile(
        "mma.sync.aligned.m16n8k16.row.col.f32.bf16.bf16.f32 "
        "{%0,%1,%2,%3}, {%4,%5,%6,%7}, {%8,%9}, {%0,%1,%2,%3};\n"
        : "+f"(c[0]), "+f"(c[1]), "+f"(c[2]), "+f"(c[3])
        : "r"(a0), "r"(a1), "r"(a2), "r"(a3), "r"(b0), "r"(b1));
}

__device__ __forceinline__ void ldsm_x4(unsigned* r, const void* p) {
    unsigned addr = (unsigned)__cvta_generic_to_shared(p);
    asm volatile("ldmatrix.sync.aligned.m8n8.x4.shared.b16 {%0,%1,%2,%3}, [%4];"
        : "=r"(r[0]), "=r"(r[1]), "=r"(r[2]), "=r"(r[3]) : "r"(addr));
}

// Issue the 24 mmas of one k16-step product-major: dependent mmas on the
// same accumulator are separated by 7 independent ones.
#define MMA_STEP_PRODMAJOR(acc, ah, al, bhf, blf)                              \
    do {                                                                       \
        _Pragma("unroll")                                                      \
        for (int nt = 0; nt < 4; nt++) {                                       \
            const unsigned b0 = bhf[nt>>1][(nt&1)*2], b1 = bhf[nt>>1][(nt&1)*2+1]; \
            _Pragma("unroll")                                                  \
            for (int mt = 0; mt < 2; mt++)                                     \
                mma16(acc[mt][nt], ah[mt][0],ah[mt][1],ah[mt][2],ah[mt][3], b0, b1); \
        }                                                                      \
        _Pragma("unroll")                                                      \
        for (int nt = 0; nt < 4; nt++) {                                       \
            const unsigned b0 = blf[nt>>1][(nt&1)*2], b1 = blf[nt>>1][(nt&1)*2+1]; \
            _Pragma("unroll")                                                  \
            for (int mt = 0; mt < 2; mt++)                                     \
                mma16(acc[mt][nt], ah[mt][0],ah[mt][1],ah[mt][2],ah[mt][3], b0, b1); \
        }                                                                      \
        _Pragma("unroll")                                                      \
        for (int nt = 0; nt < 4; nt++) {                                       \
            const unsigned b0 = bhf[nt>>1][(nt&1)*2], b1 = bhf[nt>>1][(nt&1)*2+1]; \
            _Pragma("unroll")                                                  \
            for (int mt = 0; mt < 2; mt++)                                     \
                mma16(acc[mt][nt], al[mt][0],al[mt][1],al[mt][2],al[mt][3], b0, b1); \
        }                                                                      \
    } while (0)

// ======================================================================
// Projection GEMM: C = alpha*(X @ W^T + bias); 128m x 64n tile,
// k-slab 32, double-buffered smem stages, ONE sync per slab.
// head_split: 0 = fp32 [M,N]; 1 = fp32 [B,H,S,DEP];
//             3 = V mode: split+transpose into Vth/Vtl [bh, d, npair]
// dyn smem layout (words), stage st in {0,1}, base = st*7680:
//   AH @ base, AL @ base+2560, BH @ base+5120, BL @ base+6400
// ======================================================================
__global__ __launch_bounds__(256, 2)
void gemm_xwT_bf16(const float* __restrict__ X,
                   const float* __restrict__ W,
                   const float* __restrict__ bias,
                   float* __restrict__ C,
                   unsigned* __restrict__ Vth,
                   unsigned* __restrict__ Vtl,
                   int K, int N, float alpha, int head_split)
{
    extern __shared__ unsigned dsm[];

    const int t = threadIdx.x, wid = t >> 5, lane = t & 31;
    const int gid = lane >> 2, tig = lane & 3;
    const int n0 = blockIdx.x * 64, m0 = blockIdx.y * 128;
    const int wm = (wid & 3) * 32, wn = (wid >> 2) * 32;

    const int a_r = lane & 15, a_c = ((lane >> 4) & 1) * 4;
    const int b_r = (lane & 7) + ((lane >> 4) & 1) * 8;
    const int b_c = ((lane >> 3) & 1) * 4;

    const int lr = t >> 1, lg = t & 1;   // A: row, half(16 floats)
    const int br = t >> 2, bg = t & 3;   // B: row, quarter(8 floats)

    const float* Xp = X + (size_t)(m0 + lr) * K + lg * 16;
    const float* Wp = W + (size_t)(n0 + br) * K + bg * 8;

    float acc[2][4][4];
#pragma unroll
    for (int i = 0; i < 2; i++)
#pragma unroll
        for (int j = 0; j < 4; j++)
#pragma unroll
            for (int q = 0; q < 4; q++) acc[i][j][q] = 0.0f;

    const int NS = K / 32;

    float4 xa[4], wb[2];
#pragma unroll
    for (int j = 0; j < 4; j++) xa[j] = *(const float4*)(Xp + j * 4);
#pragma unroll
    for (int j = 0; j < 2; j++) wb[j] = *(const float4*)(Wp + j * 4);

    // store slab 0 -> stage 0
    {
        unsigned* AH = dsm;            unsigned* AL = dsm + 2560;
        unsigned* BH = dsm + 5120;     unsigned* BL = dsm + 6400;
#pragma unroll
        for (int j = 0; j < 4; j++) {
            unsigned h, l;
            split2(xa[j].x, xa[j].y, h, l);
            AH[lr*20 + lg*8 + 2*j]   = h;  AL[lr*20 + lg*8 + 2*j]   = l;
            split2(xa[j].z, xa[j].w, h, l);
            AH[lr*20 + lg*8 + 2*j+1] = h;  AL[lr*20 + lg*8 + 2*j+1] = l;
        }
#pragma unroll
        for (int j = 0; j < 2; j++) {
            unsigned h, l;
            split2(wb[j].x, wb[j].y, h, l);
            BH[br*20 + bg*4 + 2*j]   = h;  BL[br*20 + bg*4 + 2*j]   = l;
            split2(wb[j].z, wb[j].w, h, l);
            BH[br*20 + bg*4 + 2*j+1] = h;  BL[br*20 + bg*4 + 2*j+1] = l;
        }
    }
    __syncthreads();

#pragma unroll 1
    for (int s = 0; s < NS; s++) {
        const int st = s & 1;
        const unsigned base = st * 7680;

        if (s + 1 < NS) {
            const int k0 = (s + 1) * 32;
#pragma unroll
            for (int j = 0; j < 4; j++) xa[j] = *(const float4*)(Xp + k0 + j * 4);
#pragma unroll
            for (int j = 0; j < 2; j++) wb[j] = *(const float4*)(Wp + k0 + j * 4);
        }

        // mma from stage st
#pragma unroll
        for (int step = 0; step < 2; step++) {
            const int kc = step * 8;
            unsigned ah[2][4], al[2][4], bhf[2][4], blf[2][4];
#pragma unroll
            for (int mt = 0; mt < 2; mt++) {
                ldsm_x4(ah[mt], dsm + base + (wm + mt*16 + a_r)*20 + kc + a_c);
                ldsm_x4(al[mt], dsm + base + 2560 + (wm + mt*16 + a_r)*20 + kc + a_c);
            }
#pragma unroll
            for (int np = 0; np < 2; np++) {
                ldsm_x4(bhf[np], dsm + base + 5120 + (wn + np*16 + b_r)*20 + kc + b_c);
                ldsm_x4(blf[np], dsm + base + 6400 + (wn + np*16 + b_r)*20 + kc + b_c);
            }
            MMA_STEP_PRODMAJOR(acc, ah, al, bhf, blf);
        }

        // store slab s+1 -> stage st^1
        if (s + 1 < NS) {
            const unsigned nb = (st ^ 1) * 7680;
            unsigned* AH = dsm + nb;          unsigned* AL = dsm + nb + 2560;
            unsigned* BH = dsm + nb + 5120;   unsigned* BL = dsm + nb + 6400;
#pragma unroll
            for (int j = 0; j < 4; j++) {
                unsigned h, l;
                split2(xa[j].x, xa[j].y, h, l);
                AH[lr*20 + lg*8 + 2*j]   = h;  AL[lr*20 + lg*8 + 2*j]   = l;
                split2(xa[j].z, xa[j].w, h, l);
                AH[lr*20 + lg*8 + 2*j+1] = h;  AL[lr*20 + lg*8 + 2*j+1] = l;
            }
#pragma unroll
            for (int j = 0; j < 2; j++) {
                unsigned h, l;
                split2(wb[j].x, wb[j].y, h, l);
                BH[br*20 + bg*4 + 2*j]   = h;  BL[br*20 + bg*4 + 2*j]   = l;
                split2(wb[j].z, wb[j].w, h, l);
                BH[br*20 + bg*4 + 2*j+1] = h;  BL[br*20 + bg*4 + 2*j+1] = l;
            }
        }
        __syncthreads();
    }

    if (head_split == 3) {
        // ---- V mode: stage fp32 tile in smem, then split+transpose out
        float* tf = (float*)dsm;   // [128][65] fp32 tile
#pragma unroll
        for (int mt = 0; mt < 2; mt++) {
#pragma unroll
            for (int nt = 0; nt < 4; nt++) {
                const int rl0 = wm + mt*16 + gid;
                const int rl1 = rl0 + 8;
                const int cl  = wn + nt*8 + tig*2;
                const float b0v = bias[n0 + cl], b1v = bias[n0 + cl + 1];
                tf[rl0*65 + cl]     = acc[mt][nt][0] + b0v;
                tf[rl0*65 + cl + 1] = acc[mt][nt][1] + b1v;
                tf[rl1*65 + cl]     = acc[mt][nt][2] + b0v;
                tf[rl1*65 + cl + 1] = acc[mt][nt][3] + b1v;
            }
        }
        __syncthreads();
        const int bb = m0 / S_, hh = n0 / DEP_;
        const int bh = bb * H_ + hh;
        const int p0 = (m0 % S_) / 2;
#pragma unroll
        for (int i = 0; i < 16; i++) {
            const int idx = t + i * 256;
            const int p = idx & 63;       // sequence pair within tile
            const int d = idx >> 6;       // 0..63
            unsigned h2, l2;
            split2(tf[(2*p)*65 + d], tf[(2*p + 1)*65 + d], h2, l2);
            const size_t o = ((size_t)bh * DEP_ + d) * (S_/2) + p0 + p;
            Vth[o] = h2;
            Vtl[o] = l2;
        }
        return;
    }

#pragma unroll
    for (int mt = 0; mt < 2; mt++) {
#pragma unroll
        for (int nt = 0; nt < 4; nt++) {
            const int r0 = m0 + wm + mt*16 + gid;
            const int r1 = r0 + 8;
            const int c  = n0 + wn + nt*8 + tig*2;
            const float b0v = bias[c], b1v = bias[c+1];
            float2 v0, v1;
            v0.x = alpha * (acc[mt][nt][0] + b0v);
            v0.y = alpha * (acc[mt][nt][1] + b1v);
            v1.x = alpha * (acc[mt][nt][2] + b0v);
            v1.y = alpha * (acc[mt][nt][3] + b1v);
            if (head_split == 1) {
                const int h = n0 / DEP_;
                const int dd = c - n0;
                const int b0_ = r0 / S_, s0 = r0 % S_;
                const int b1_ = r1 / S_, s1 = r1 % S_;
                *(float2*)(C + (((size_t)(b0_*H_ + h))*S_ + s0)*DEP_ + dd) = v0;
                *(float2*)(C + (((size_t)(b1_*H_ + h))*S_ + s1)*DEP_ + dd) = v1;
            } else {
                *(float2*)(C + (size_t)r0 * N + c) = v0;
                *(float2*)(C + (size_t)r1 * N + c) = v1;
            }
        }
    }
}

// ======================================================================
// logits: 128m x 256n strip; A(Q) smem-resident (both k-slabs),
// B double-buffered, ONE sync per iteration; fused online stats.
// dyn smem (words): AH slab s @ s*2560, AL @ 5120 + s*2560,
//   B stage st: BH @ 10240 + st*2560, BL @ +1280. grid (8, 16, 24)
// ======================================================================
__global__ __launch_bounds__(256, 2)
void logits_bf16(const float* __restrict__ Qp,
                 const float* __restrict__ Kp,
                 const int*   __restrict__ mask,
                 float* __restrict__ attn,
                 float* __restrict__ cmax,
                 float* __restrict__ csum)
{
    extern __shared__ unsigned dsm[];
    __shared__ int   smask[256];
    __shared__ float smx[2][128], ssm[2][128];

    const int t = threadIdx.x, wid = t >> 5, lane = t & 31;
    const int gid = lane >> 2, tig = lane & 3;
    const int nbase = blockIdx.x * 256, m0 = blockIdx.y * 128;
    const int bh = blockIdx.z, b = bh / H_;
    const int wm = (wid & 3) * 32, wn = (wid >> 2) * 32;
    const int hf = wid >> 2;

    const int a_r = lane & 15, a_c = ((lane >> 4) & 1) * 4;
    const int b_r = (lane & 7) + ((lane >> 4) & 1) * 8;
    const int b_c = ((lane >> 3) & 1) * 4;

    smask[t] = mask[b * S_ + nbase + t];

    const int br = t >> 2, bg = t & 3;

    // ---- A: load full K=64 into smem (slab = t&1, row = t>>1)
    {
        const int slab = t & 1, row = t >> 1;
        const float* Qb = Qp + ((size_t)bh * S_ + m0 + row) * DEP_ + slab * 32;
        unsigned* AH = dsm + slab * 2560;
        unsigned* AL = dsm + 5120 + slab * 2560;
#pragma unroll
        for (int g = 0; g < 4; g++) {
            float4 f0 = *(const float4*)(Qb + g * 8);
            float4 f1 = *(const float4*)(Qb + g * 8 + 4);
            unsigned h, l;
            split2(f0.x, f0.y, h, l);
            AH[row*20 + g*4 + 0] = h;  AL[row*20 + g*4 + 0] = l;
            split2(f0.z, f0.w, h, l);
            AH[row*20 + g*4 + 1] = h;  AL[row*20 + g*4 + 1] = l;
            split2(f1.x, f1.y, h, l);
            AH[row*20 + g*4 + 2] = h;  AL[row*20 + g*4 + 2] = l;
            split2(f1.z, f1.w, h, l);
            AH[row*20 + g*4 + 3] = h;  AL[row*20 + g*4 + 3] = l;
        }
    }

    // ---- B it=0 load + store into stage 0
    float4 wb[2];
    {
        const float* Kb = Kp + ((size_t)bh * S_ + nbase + br) * DEP_ + bg * 8;
#pragma unroll
        for (int j = 0; j < 2; j++) wb[j] = *(const float4*)(Kb + j * 4);
        unsigned* BH = dsm + 10240;
        unsigned* BL = dsm + 10240 + 1280;
#pragma unroll
        for (int j = 0; j < 2; j++) {
            unsigned h, l;
            split2(wb[j].x, wb[j].y, h, l);
            BH[br*20 + bg*4 + 2*j]   = h;  BL[br*20 + bg*4 + 2*j]   = l;
            split2(wb[j].z, wb[j].w, h, l);
            BH[br*20 + bg*4 + 2*j+1] = h;  BL[br*20 + bg*4 + 2*j+1] = l;
        }
    }
    __syncthreads();

    float runm[2][2], runs[2][2];
#pragma unroll
    for (int i = 0; i < 2; i++)
#pragma unroll
        for (int j = 0; j < 2; j++) { runm[i][j] = neg_inf(); runs[i][j] = 0.0f; }

    float acc[2][4][4];
    float* Cb = attn + (size_t)bh * S_ * S_;

#pragma unroll
    for (int it = 0; it < 8; it++) {
        const int ni = it >> 1, ks = it & 1, st = it & 1;
        if (ks == 0) {
#pragma unroll
            for (int i = 0; i < 2; i++)
#pragma unroll
                for (int j = 0; j < 4; j++)
#pragma unroll
                    for (int q = 0; q < 4; q++) acc[i][j][q] = 0.0f;
        }

        if (it + 1 < 8) {
            const int niN = (it+1) >> 1, ksN = (it+1) & 1;
            const float* Kb = Kp + ((size_t)bh * S_ + nbase + niN*64 + br) * DEP_
                              + ksN*32 + bg*8;
#pragma unroll
            for (int j = 0; j < 2; j++) wb[j] = *(const float4*)(Kb + j * 4);
        }

        // ---- mma: A slab ks, B stage st
#pragma unroll
        for (int step = 0; step < 2; step++) {
            const int kc = step * 8;
            unsigned ah[2][4], al[2][4], bhf[2][4], blf[2][4];
#pragma unroll
            for (int mt = 0; mt < 2; mt++) {
                ldsm_x4(ah[mt], dsm + ks*2560        + (wm + mt*16 + a_r)*20 + kc + a_c);
                ldsm_x4(al[mt], dsm + 5120 + ks*2560 + (wm + mt*16 + a_r)*20 + kc + a_c);
            }
#pragma unroll
            for (int np = 0; np < 2; np++) {
                ldsm_x4(bhf[np], dsm + 10240 + st*2560        + (wn + np*16 + b_r)*20 + kc + b_c);
                ldsm_x4(blf[np], dsm + 10240 + st*2560 + 1280 + (wn + np*16 + b_r)*20 + kc + b_c);
            }
            MMA_STEP_PRODMAJOR(acc, ah, al, bhf, blf);
        }

        if (ks == 1) {
            bool mz[4][2];
#pragma unroll
            for (int nt = 0; nt < 4; nt++) {
                const int lc = ni*64 + wn + nt*8 + tig*2;
                mz[nt][0] = (smask[lc] == 0);
                mz[nt][1] = (smask[lc+1] == 0);
            }
#pragma unroll
            for (int mt = 0; mt < 2; mt++) {
#pragma unroll
                for (int nt = 0; nt < 4; nt++) {
                    const int r0 = m0 + wm + mt*16 + gid;
                    const int r1 = r0 + 8;
                    const int c  = nbase + ni*64 + wn + nt*8 + tig*2;
                    float2 v0, v1;
                    v0.x = mz[nt][0] ? neg_inf() : acc[mt][nt][0];
                    v0.y = mz[nt][1] ? neg_inf() : acc[mt][nt][1];
                    v1.x = mz[nt][0] ? neg_inf() : acc[mt][nt][2];
                    v1.y = mz[nt][1] ? neg_inf() : acc[mt][nt][3];
                    *(float2*)(Cb + (size_t)r0 * S_ + c) = v0;
                    *(float2*)(Cb + (size_t)r1 * S_ + c) = v1;
                }
            }
#pragma unroll
            for (int mt = 0; mt < 2; mt++) {
#pragma unroll
                for (int rh = 0; rh < 2; rh++) {
                    float mx = neg_inf();
#pragma unroll
                    for (int nt = 0; nt < 4; nt++) {
                        float v0 = mz[nt][0] ? neg_inf() : acc[mt][nt][rh*2];
                        float v1 = mz[nt][1] ? neg_inf() : acc[mt][nt][rh*2+1];
                        mx = fmaxf(mx, fmaxf(v0, v1));
                    }
                    mx = fmaxf(mx, __shfl_xor_sync(0xffffffffu, mx, 1));
                    mx = fmaxf(mx, __shfl_xor_sync(0xffffffffu, mx, 2));
                    float s = 0.0f;
                    if (mx != neg_inf()) {
#pragma unroll
                        for (int nt = 0; nt < 4; nt++) {
                            if (!mz[nt][0]) s += __expf(acc[mt][nt][rh*2]   - mx);
                            if (!mz[nt][1]) s += __expf(acc[mt][nt][rh*2+1] - mx);
                        }
                    }
                    s += __shfl_xor_sync(0xffffffffu, s, 1);
                    s += __shfl_xor_sync(0xffffffffu, s, 2);
                    if (mx > runm[mt][rh]) {
                        runs[mt][rh] = runs[mt][rh] * __expf(runm[mt][rh] - mx) + s;
                        runm[mt][rh] = mx;
                    } else if (mx != neg_inf()) {
                        runs[mt][rh] += s * __expf(mx - runm[mt][rh]);
                    }
                }
            }
        }

        // ---- store B it+1 into stage st^1
        if (it + 1 < 8) {
            unsigned* BH = dsm + 10240 + (st^1)*2560;
            unsigned* BL = BH + 1280;
#pragma unroll
            for (int j = 0; j < 2; j++) {
                unsigned h, l;
                split2(wb[j].x, wb[j].y, h, l);
                BH[br*20 + bg*4 + 2*j]   = h;  BL[br*20 + bg*4 + 2*j]   = l;
                split2(wb[j].z, wb[j].w, h, l);
                BH[br*20 + bg*4 + 2*j+1] = h;  BL[br*20 + bg*4 + 2*j+1] = l;
            }
        }
        __syncthreads();
    }

    // ---- cross-half combine + write chunk partials
    if (tig == 0) {
#pragma unroll
        for (int mt = 0; mt < 2; mt++)
#pragma unroll
            for (int rh = 0; rh < 2; rh++) {
                const int row = wm + mt*16 + rh*8 + gid;
                smx[hf][row] = runm[mt][rh];
                ssm[hf][row] = runs[mt][rh];
            }
    }
    __syncthreads();
    if (t < 128) {
        const float m0v = smx[0][t], m1v = smx[1][t];
        const float s0 = ssm[0][t], s1 = ssm[1][t];
        const float M = fmaxf(m0v, m1v);
        float S = 0.0f;
        if (m0v != neg_inf()) S += s0 * __expf(m0v - M);
        if (m1v != neg_inf()) S += s1 * __expf(m1v - M);
        const size_t row = (size_t)bh * S_ + m0 + t;
        cmax[row * NCHUNK + blockIdx.x] = M;
        csum[row * NCHUNK + blockIdx.x] = S;
    }
}

// ======================================================================
__global__ __launch_bounds__(256)
void chunk_reduce(const float* __restrict__ cmax,
                  const float* __restrict__ csum,
                  float* __restrict__ gmax,
                  float* __restrict__ ginv)
{
    const int r = blockIdx.x * 256 + threadIdx.x;
    if (r >= BH_ * S_) return;
    float M = neg_inf(), S = 0.0f;
#pragma unroll
    for (int c = 0; c < NCHUNK; c++) {
        const float m = cmax[(size_t)r * NCHUNK + c];
        const float s = csum[(size_t)r * NCHUNK + c];
        if (m > M) { S = S * __expf(M - m) + s; M = m; }
        else if (m != neg_inf()) { S += s * __expf(m - M); }
    }
    gmax[r] = M;
    ginv[r] = 1.0f / S;
}

// ======================================================================
// ctx: double-buffered A and V stages, ONE sync per 32-n slab.
// dyn smem (words): A stage st: AH @ st*5120, AL @ st*5120+2560;
//   V stage st: VH @ 10240 + st*2560, VL @ +1280. grid (16, 24)
// ======================================================================
__global__ __launch_bounds__(256, 2)
void ctx_bf16(float* __restrict__ attn,
              const unsigned* __restrict__ Vth,
              const unsigned* __restrict__ Vtl,
              const float* __restrict__ gmax,
              const float* __restrict__ ginv,
              float* __restrict__ ctx)
{
    extern __shared__ unsigned dsm[];

    const int t = threadIdx.x, wid = t >> 5, lane = t & 31;
    const int gid = lane >> 2, tig = lane & 3;
    const int m0 = blockIdx.x * 128;
    const int bh = blockIdx.y;
    const int b  = bh / H_, h = bh % H_;
    const int wm = (wid & 3) * 32, wd = (wid >> 2) * 32;

    const int a_r = lane & 15, a_c = ((lane >> 4) & 1) * 4;
    const int b_r = (lane & 7) + ((lane >> 4) & 1) * 8;
    const int b_c = ((lane >> 3) & 1) * 4;

    const int lr = t >> 1, lg = t & 1;
    const int vr = t >> 2, vg = t & 3;

    float* Ap = attn + ((size_t)bh * S_ + m0 + lr) * S_ + lg * 16;
    const unsigned* VthB = Vth + ((size_t)bh * DEP_ + vr) * (S_/2) + vg * 4;
    const unsigned* VtlB = Vtl + ((size_t)bh * DEP_ + vr) * (S_/2) + vg * 4;

    const float mr = gmax[bh * S_ + m0 + lr];
    const float ir = ginv[bh * S_ + m0 + lr];

    float acc[2][4][4];
#pragma unroll
    for (int i = 0; i < 2; i++)
#pragma unroll
        for (int j = 0; j < 4; j++)
#pragma unroll
            for (int q = 0; q < 4; q++) acc[i][j][q] = 0.0f;

    float4 av[4];
    uint4 vh4, vl4;

    // ---- prologue: slab 0 -> stage 0
#pragma unroll
    for (int j = 0; j < 4; j++) av[j] = *(const float4*)(Ap + j * 4);
    vh4 = *(const uint4*)(VthB);
    vl4 = *(const uint4*)(VtlB);
    {
        unsigned* AH = dsm;          unsigned* AL = dsm + 2560;
        unsigned* VH = dsm + 10240;  unsigned* VL = dsm + 10240 + 1280;
#pragma unroll
        for (int j = 0; j < 4; j++) {
            float4 pv;
            pv.x = __expf(av[j].x - mr) * ir;
            pv.y = __expf(av[j].y - mr) * ir;
            pv.z = __expf(av[j].z - mr) * ir;
            pv.w = __expf(av[j].w - mr) * ir;
            *(float4*)(Ap + j * 4) = pv;
            unsigned hh, ll;
            split2(pv.x, pv.y, hh, ll);
            AH[lr*20 + lg*8 + 2*j]   = hh;  AL[lr*20 + lg*8 + 2*j]   = ll;
            split2(pv.z, pv.w, hh, ll);
            AH[lr*20 + lg*8 + 2*j+1] = hh;  AL[lr*20 + lg*8 + 2*j+1] = ll;
        }
        *(uint4*)&VH[vr*20 + vg*4] = vh4;
        *(uint4*)&VL[vr*20 + vg*4] = vl4;
    }
    __syncthreads();

#pragma unroll 1
    for (int i = 0; i < 64; i++) {
        const int st = i & 1;

        if (i + 1 < 64) {
            const int nc = (i + 1) * 32;
#pragma unroll
            for (int j = 0; j < 4; j++) av[j] = *(const float4*)(Ap + nc + j * 4);
            vh4 = *(const uint4*)(VthB + nc/2);
            vl4 = *(const uint4*)(VtlB + nc/2);
        }

        // ---- mma from stage st
#pragma unroll
        for (int step = 0; step < 2; step++) {
            const int kc = step * 8;
            unsigned ah[2][4], al[2][4], bhf[2][4], blf[2][4];
#pragma unroll
            for (int mt = 0; mt < 2; mt++) {
                ldsm_x4(ah[mt], dsm + st*5120        + (wm + mt*16 + a_r)*20 + kc + a_c);
                ldsm_x4(al[mt], dsm + st*5120 + 2560 + (wm + mt*16 + a_r)*20 + kc + a_c);
            }
#pragma unroll
            for (int np = 0; np < 2; np++) {
                ldsm_x4(bhf[np], dsm + 10240 + st*2560        + (wd + np*16 + b_r)*20 + kc + b_c);
                ldsm_x4(blf[np], dsm + 10240 + st*2560 + 1280 + (wd + np*16 + b_r)*20 + kc + b_c);
            }
            MMA_STEP_PRODMAJOR(acc, ah, al, bhf, blf);
        }

        // ---- process slab i+1 -> stage st^1
        if (i + 1 < 64) {
            const int nc = (i + 1) * 32;
            const unsigned ab = (st ^ 1) * 5120;
            unsigned* AH = dsm + ab;            unsigned* AL = dsm + ab + 2560;
            unsigned* VH = dsm + 10240 + (st^1)*2560;
            unsigned* VL = VH + 1280;
#pragma unroll
            for (int j = 0; j < 4; j++) {
                float4 pv;
                pv.x = __expf(av[j].x - mr) * ir;
                pv.y = __expf(av[j].y - mr) * ir;
                pv.z = __expf(av[j].z - mr) * ir;
                pv.w = __expf(av[j].w - mr) * ir;
                *(float4*)(Ap + nc + j * 4) = pv;
                unsigned hh, ll;
                split2(pv.x, pv.y, hh, ll);
                AH[lr*20 + lg*8 + 2*j]   = hh;  AL[lr*20 + lg*8 + 2*j]   = ll;
                split2(pv.z, pv.w, hh, ll);
                AH[lr*20 + lg*8 + 2*j+1] = hh;  AL[lr*20 + lg*8 + 2*j+1] = ll;
            }
            *(uint4*)&VH[vr*20 + vg*4] = vh4;
            *(uint4*)&VL[vr*20 + vg*4] = vl4;
        }
        __syncthreads();
    }

#pragma unroll
    for (int mt = 0; mt < 2; mt++) {
#pragma unroll
        for (int dt = 0; dt < 4; dt++) {
            const int r0 = m0 + wm + mt*16 + gid;
            const int r1 = r0 + 8;
            const int d  = wd + dt*8 + tig*2;
            float2 v0 = {acc[mt][dt][0], acc[mt][dt][1]};
            float2 v1 = {acc[mt][dt][2], acc[mt][dt][3]};
            *(float2*)(ctx + ((size_t)b * S_ + r0) * D_ + h * DEP_ + d) = v0;
            *(float2*)(ctx + ((size_t)b * S_ + r1) * D_ + h * DEP_ + d) = v1;
        }
    }
}

// ======================================================================
extern "C" void kernel_launch(void* const* d_in, const int* in_sizes, int n_in,
                              void* d_out, int out_size)
{
    const float* q    = (const float*)d_in[0];
    const float* k    = (const float*)d_in[1];
    const float* v    = (const float*)d_in[2];
    const int*   mask = (const int*)  d_in[3];
    const float* wq_w = (const float*)d_in[4];
    const float* wq_b = (const float*)d_in[5];
    const float* wk_w = (const float*)d_in[6];
    const float* wk_b = (const float*)d_in[7];
    const float* wv_w = (const float*)d_in[8];
    const float* wv_b = (const float*)d_in[9];
    const float* wo_w = (const float*)d_in[10];
    const float* wo_b = (const float*)d_in[11];
    float* out = (float*)d_out;

    float *Qp, *Kp, *ctxp, *rmax, *rinv, *cmax, *csum, *attn_s;
    unsigned *Vth, *Vtl;
    cudaGetSymbolAddress((void**)&Qp,     g_Qp);
    cudaGetSymbolAddress((void**)&Kp,     g_Kp);
    cudaGetSymbolAddress((void**)&ctxp,   g_ctx);
    cudaGetSymbolAddress((void**)&rmax,   g_rowmax);
    cudaGetSymbolAddress((void**)&rinv,   g_rowinv);
    cudaGetSymbolAddress((void**)&cmax,   g_cmax);
    cudaGetSymbolAddress((void**)&csum,   g_csum);
    cudaGetSymbolAddress((void**)&Vth,    g_Vth);
    cudaGetSymbolAddress((void**)&Vtl,    g_Vtl);
    cudaGetSymbolAddress((void**)&attn_s, g_attn_scratch);

    const long long need = (long long)OUT_ELEMS + (long long)ATTN_ELEMS;
    float* attn = ((long long)out_size >= need) ? (out + OUT_ELEMS) : attn_s;

    cudaFuncSetAttribute(gemm_xwT_bf16,
                         cudaFuncAttributeMaxDynamicSharedMemorySize, DYN_SMEM_BYTES);
    cudaFuncSetAttribute(logits_bf16,
                         cudaFuncAttributeMaxDynamicSharedMemorySize, DYN_SMEM_BYTES);
    cudaFuncSetAttribute(ctx_bf16,
                         cudaFuncAttributeMaxDynamicSharedMemorySize, DYN_SMEM_BYTES);

    // Q/K/V projections (Q pre-scaled by 1/8); V projection writes split
    // transposed Vth/Vtl directly (mode 3).
    dim3 pgrid(D_/64, MROWS/128);
    gemm_xwT_bf16<<<pgrid, 256, DYN_SMEM_BYTES>>>(q, wq_w, wq_b, Qp,
                                                  nullptr, nullptr,
                                                  D_, D_, 0.125f, 1);
    gemm_xwT_bf16<<<pgrid, 256, DYN_SMEM_BYTES>>>(k, wk_w, wk_b, Kp,
                                                  nullptr, nullptr,
                                                  D_, D_, 1.0f, 1);
    gemm_xwT_bf16<<<pgrid, 256, DYN_SMEM_BYTES>>>(v, wv_w, wv_b, nullptr,
                                                  Vth, Vtl,
                                                  D_, D_, 1.0f, 3);

    // raw masked logits + per-chunk softmax partials
    logits_bf16<<<dim3(S_/256, S_/128, BH_), 256, DYN_SMEM_BYTES>>>(
        Qp, Kp, mask, attn, cmax, csum);

    // combine partials -> row stats
    chunk_reduce<<<dim3((BH_*S_ + 255)/256), 256>>>(cmax, csum, rmax, rinv);

    // ctx = softmax @ V; normalizes attn in place
    ctx_bf16<<<dim3(S_/128, BH_), 256, DYN_SMEM_BYTES>>>(
        attn, Vth, Vtl, rmax, rinv, ctxp);

    // output projection
    gemm_xwT_bf16<<<pgrid, 256, DYN_SMEM_BYTES>>>(ctxp, wo_w, wo_b, out,
                                                  nullptr, nullptr,
                                                  D_, D_, 1.0f, 0);
}

// round 16
// speedup vs baseline: 1.5246x; 1.0599x over previous
#include <cuda_runtime.h>
#include <cuda_bf16.h>
#include <math.h>

#define B_    2
#define S_    2048
#define D_    768
#define H_    12
#define DEP_  64
#define BH_   (B_*H_)            // 24
#define MROWS (B_*S_)            // 4096
#define OUT_ELEMS (B_*S_*D_)     // 3145728
#define ATTN_ELEMS (BH_*S_*S_)   // 100663296
#define NCHUNK 8

#define DYN_SMEM_BYTES 61440     // 15360 words, all three mma kernels

// ---- scratch (alloc-free, __device__ globals) ----
__device__ float g_Qp[BH_*S_*DEP_];
__device__ float g_Kp[BH_*S_*DEP_];
__device__ float g_ctx[MROWS*D_];
__device__ float g_rowmax[BH_*S_];
__device__ float g_rowinv[BH_*S_];
__device__ float g_cmax[BH_*S_*NCHUNK];
__device__ float g_csum[BH_*S_*NCHUNK];
__device__ unsigned g_Vth[BH_*DEP_*(S_/2)];
__device__ unsigned g_Vtl[BH_*DEP_*(S_/2)];
__device__ float g_attn_scratch[ATTN_ELEMS];

__device__ __forceinline__ float neg_inf() { return __int_as_float(0xff800000); }

__device__ __forceinline__ void split2(float x, float y, unsigned& h, unsigned& l) {
    __nv_bfloat162 hv = __floats2bfloat162_rn(x, y);
    float2 hf = __bfloat1622float2(hv);
    __nv_bfloat162 lv = __floats2bfloat162_rn(x - hf.x, y - hf.y);
    h = *(unsigned*)&hv;
    l = *(unsigned*)&lv;
}

__device__ __forceinline__ void mma16(float* c,
                                      unsigned a0, unsigned a1, unsigned a2, unsigned a3,
                                      unsigned b0, unsigned b1) {
    asm volatile(
        "mma.sync.aligned.m16n8k16.row.col.f32.bf16.bf16.f32 "
        "{%0,%1,%2,%3}, {%4,%5,%6,%7}, {%8,%9}, {%0,%1,%2,%3};\n"
        : "+f"(c[0]), "+f"(c[1]), "+f"(c[2]), "+f"(c[3])
        : "r"(a0), "r"(a1), "r"(a2), "r"(a3), "r"(b0), "r"(b1));
}

__device__ __forceinline__ void ldsm_x4(unsigned* r, const void* p) {
    unsigned addr = (unsigned)__cvta_generic_to_shared(p);
    asm volatile("ldmatrix.sync.aligned.m8n8.x4.shared.b16 {%0,%1,%2,%3}, [%4];"
        : "=r"(r[0]), "=r"(r[1]), "=r"(r[2]), "=r"(r[3]) : "r"(addr));
}

// 24 mmas of one k16-step, product-major (kept from R15; neutral but harmless)
#define MMA_STEP_PRODMAJOR(acc, ah, al, bhf, blf)                              \
    do {                                                                       \
        _Pragma("unroll")                                                      \
        for (int nt = 0; nt < 4; nt++) {                                       \
            const unsigned b0 = bhf[nt>>1][(nt&1)*2], b1 = bhf[nt>>1][(nt&1)*2+1]; \
            _Pragma("unroll")                                                  \
            for (int mt = 0; mt < 2; mt++)                                     \
                mma16(acc[mt][nt], ah[mt][0],ah[mt][1],ah[mt][2],ah[mt][3], b0, b1); \
        }                                                                      \
        _Pragma("unroll")                                                      \
        for (int nt = 0; nt < 4; nt++) {                                       \
            const unsigned b0 = blf[nt>>1][(nt&1)*2], b1 = blf[nt>>1][(nt&1)*2+1]; \
            _Pragma("unroll")                                                  \
            for (int mt = 0; mt < 2; mt++)                                     \
                mma16(acc[mt][nt], ah[mt][0],ah[mt][1],ah[mt][2],ah[mt][3], b0, b1); \
        }                                                                      \
        _Pragma("unroll")                                                      \
        for (int nt = 0; nt < 4; nt++) {                                       \
            const unsigned b0 = bhf[nt>>1][(nt&1)*2], b1 = bhf[nt>>1][(nt&1)*2+1]; \
            _Pragma("unroll")                                                  \
            for (int mt = 0; mt < 2; mt++)                                     \
                mma16(acc[mt][nt], al[mt][0],al[mt][1],al[mt][2],al[mt][3], b0, b1); \
        }                                                                      \
    } while (0)

// ======================================================================
// Fused Q/K/V projection GEMM: one launch, grid.z selects the projection.
//   z=0: Qp = 0.125*(q @ wq^T + bq)   [B,H,S,DEP] fp32
//   z=1: Kp = k @ wk^T + bk           [B,H,S,DEP] fp32
//   z=2: V  = v @ wv^T + bv -> split+transpose into Vth/Vtl
// Also used standalone (gridDim.z==1) for the output projection (mode 0).
// 128m x 64n tile, k-slab 32, double-buffered, ONE sync per slab.
// ======================================================================
__global__ __launch_bounds__(256, 2)
void gemm_xwT_bf16(const float* __restrict__ X0, const float* __restrict__ X1,
                   const float* __restrict__ X2,
                   const float* __restrict__ W0, const float* __restrict__ W1,
                   const float* __restrict__ W2,
                   const float* __restrict__ bias0, const float* __restrict__ bias1,
                   const float* __restrict__ bias2,
                   float* __restrict__ C0, float* __restrict__ C1,
                   unsigned* __restrict__ Vth, unsigned* __restrict__ Vtl,
                   int K, int N, int fused)
{
    extern __shared__ unsigned dsm[];

    const int t = threadIdx.x, wid = t >> 5, lane = t & 31;
    const int gid = lane >> 2, tig = lane & 3;
    const int n0 = blockIdx.x * 64, m0 = blockIdx.y * 128;
    const int z  = blockIdx.z;
    const int wm = (wid & 3) * 32, wn = (wid >> 2) * 32;

    // per-z operand selection
    const float* X    = (z == 0) ? X0 : (z == 1) ? X1 : X2;
    const float* W    = (z == 0) ? W0 : (z == 1) ? W1 : W2;
    const float* bias = (z == 0) ? bias0 : (z == 1) ? bias1 : bias2;
    // mode: fused ? (z==2 ? 3 : 1) : 0 ; alpha: z==0 && fused ? 0.125 : 1
    const int   mode  = fused ? ((z == 2) ? 3 : 1) : 0;
    const float alpha = (fused && z == 0) ? 0.125f : 1.0f;
    float* C          = (z == 0) ? C0 : C1;   // mode3 ignores C

    const int a_r = lane & 15, a_c = ((lane >> 4) & 1) * 4;
    const int b_r = (lane & 7) + ((lane >> 4) & 1) * 8;
    const int b_c = ((lane >> 3) & 1) * 4;

    const int lr = t >> 1, lg = t & 1;   // A: row, half(16 floats)
    const int br = t >> 2, bg = t & 3;   // B: row, quarter(8 floats)

    const float* Xp = X + (size_t)(m0 + lr) * K + lg * 16;
    const float* Wp = W + (size_t)(n0 + br) * K + bg * 8;

    float acc[2][4][4];
#pragma unroll
    for (int i = 0; i < 2; i++)
#pragma unroll
        for (int j = 0; j < 4; j++)
#pragma unroll
            for (int q = 0; q < 4; q++) acc[i][j][q] = 0.0f;

    const int NS = K / 32;

    float4 xa[4], wb[2];
#pragma unroll
    for (int j = 0; j < 4; j++) xa[j] = *(const float4*)(Xp + j * 4);
#pragma unroll
    for (int j = 0; j < 2; j++) wb[j] = *(const float4*)(Wp + j * 4);

    // store slab 0 -> stage 0
    {
        unsigned* AH = dsm;            unsigned* AL = dsm + 2560;
        unsigned* BH = dsm + 5120;     unsigned* BL = dsm + 6400;
#pragma unroll
        for (int j = 0; j < 4; j++) {
            unsigned h, l;
            split2(xa[j].x, xa[j].y, h, l);
            AH[lr*20 + lg*8 + 2*j]   = h;  AL[lr*20 + lg*8 + 2*j]   = l;
            split2(xa[j].z, xa[j].w, h, l);
            AH[lr*20 + lg*8 + 2*j+1] = h;  AL[lr*20 + lg*8 + 2*j+1] = l;
        }
#pragma unroll
        for (int j = 0; j < 2; j++) {
            unsigned h, l;
            split2(wb[j].x, wb[j].y, h, l);
            BH[br*20 + bg*4 + 2*j]   = h;  BL[br*20 + bg*4 + 2*j]   = l;
            split2(wb[j].z, wb[j].w, h, l);
            BH[br*20 + bg*4 + 2*j+1] = h;  BL[br*20 + bg*4 + 2*j+1] = l;
        }
    }
    __syncthreads();

#pragma unroll 1
    for (int s = 0; s < NS; s++) {
        const int st = s & 1;
        const unsigned base = st * 7680;

        if (s + 1 < NS) {
            const int k0 = (s + 1) * 32;
#pragma unroll
            for (int j = 0; j < 4; j++) xa[j] = *(const float4*)(Xp + k0 + j * 4);
#pragma unroll
            for (int j = 0; j < 2; j++) wb[j] = *(const float4*)(Wp + k0 + j * 4);
        }

        // mma from stage st
#pragma unroll
        for (int step = 0; step < 2; step++) {
            const int kc = step * 8;
            unsigned ah[2][4], al[2][4], bhf[2][4], blf[2][4];
#pragma unroll
            for (int mt = 0; mt < 2; mt++) {
                ldsm_x4(ah[mt], dsm + base + (wm + mt*16 + a_r)*20 + kc + a_c);
                ldsm_x4(al[mt], dsm + base + 2560 + (wm + mt*16 + a_r)*20 + kc + a_c);
            }
#pragma unroll
            for (int np = 0; np < 2; np++) {
                ldsm_x4(bhf[np], dsm + base + 5120 + (wn + np*16 + b_r)*20 + kc + b_c);
                ldsm_x4(blf[np], dsm + base + 6400 + (wn + np*16 + b_r)*20 + kc + b_c);
            }
            MMA_STEP_PRODMAJOR(acc, ah, al, bhf, blf);
        }

        // store slab s+1 -> stage st^1
        if (s + 1 < NS) {
            const unsigned nb = (st ^ 1) * 7680;
            unsigned* AH = dsm + nb;          unsigned* AL = dsm + nb + 2560;
            unsigned* BH = dsm + nb + 5120;   unsigned* BL = dsm + nb + 6400;
#pragma unroll
            for (int j = 0; j < 4; j++) {
                unsigned h, l;
                split2(xa[j].x, xa[j].y, h, l);
                AH[lr*20 + lg*8 + 2*j]   = h;  AL[lr*20 + lg*8 + 2*j]   = l;
                split2(xa[j].z, xa[j].w, h, l);
                AH[lr*20 + lg*8 + 2*j+1] = h;  AL[lr*20 + lg*8 + 2*j+1] = l;
            }
#pragma unroll
            for (int j = 0; j < 2; j++) {
                unsigned h, l;
                split2(wb[j].x, wb[j].y, h, l);
                BH[br*20 + bg*4 + 2*j]   = h;  BL[br*20 + bg*4 + 2*j]   = l;
                split2(wb[j].z, wb[j].w, h, l);
                BH[br*20 + bg*4 + 2*j+1] = h;  BL[br*20 + bg*4 + 2*j+1] = l;
            }
        }
        __syncthreads();
    }

    if (mode == 3) {
        // ---- V mode: stage fp32 tile in smem, then split+transpose out
        float* tf = (float*)dsm;   // [128][65] fp32 tile
#pragma unroll
        for (int mt = 0; mt < 2; mt++) {
#pragma unroll
            for (int nt = 0; nt < 4; nt++) {
                const int rl0 = wm + mt*16 + gid;
                const int rl1 = rl0 + 8;
                const int cl  = wn + nt*8 + tig*2;
                const float b0v = bias[n0 + cl], b1v = bias[n0 + cl + 1];
                tf[rl0*65 + cl]     = acc[mt][nt][0] + b0v;
                tf[rl0*65 + cl + 1] = acc[mt][nt][1] + b1v;
                tf[rl1*65 + cl]     = acc[mt][nt][2] + b0v;
                tf[rl1*65 + cl + 1] = acc[mt][nt][3] + b1v;
            }
        }
        __syncthreads();
        const int bb = m0 / S_, hh = n0 / DEP_;
        const int bh = bb * H_ + hh;
        const int p0 = (m0 % S_) / 2;
#pragma unroll
        for (int i = 0; i < 16; i++) {
            const int idx = t + i * 256;
            const int p = idx & 63;       // sequence pair within tile
            const int d = idx >> 6;       // 0..63
            unsigned h2, l2;
            split2(tf[(2*p)*65 + d], tf[(2*p + 1)*65 + d], h2, l2);
            const size_t o = ((size_t)bh * DEP_ + d) * (S_/2) + p0 + p;
            Vth[o] = h2;
            Vtl[o] = l2;
        }
        return;
    }

#pragma unroll
    for (int mt = 0; mt < 2; mt++) {
#pragma unroll
        for (int nt = 0; nt < 4; nt++) {
            const int r0 = m0 + wm + mt*16 + gid;
            const int r1 = r0 + 8;
            const int c  = n0 + wn + nt*8 + tig*2;
            const float b0v = bias[c], b1v = bias[c+1];
            float2 v0, v1;
            v0.x = alpha * (acc[mt][nt][0] + b0v);
            v0.y = alpha * (acc[mt][nt][1] + b1v);
            v1.x = alpha * (acc[mt][nt][2] + b0v);
            v1.y = alpha * (acc[mt][nt][3] + b1v);
            if (mode == 1) {
                const int h = n0 / DEP_;
                const int dd = c - n0;
                const int b0_ = r0 / S_, s0 = r0 % S_;
                const int b1_ = r1 / S_, s1 = r1 % S_;
                *(float2*)(C + (((size_t)(b0_*H_ + h))*S_ + s0)*DEP_ + dd) = v0;
                *(float2*)(C + (((size_t)(b1_*H_ + h))*S_ + s1)*DEP_ + dd) = v1;
            } else {
                *(float2*)(C + (size_t)r0 * N + c) = v0;
                *(float2*)(C + (size_t)r1 * N + c) = v1;
            }
        }
    }
}

// ======================================================================
// logits: 128m x 256n strip; A(Q) smem-resident (both k-slabs),
// B double-buffered, ONE sync per iteration; fused online stats.
// dyn smem (words): AH slab s @ s*2560, AL @ 5120 + s*2560,
//   B stage st: BH @ 10240 + st*2560, BL @ +1280. grid (8, 16, 24)
// ======================================================================
__global__ __launch_bounds__(256, 2)
void logits_bf16(const float* __restrict__ Qp,
                 const float* __restrict__ Kp,
                 const int*   __restrict__ mask,
                 float* __restrict__ attn,
                 float* __restrict__ cmax,
                 float* __restrict__ csum)
{
    extern __shared__ unsigned dsm[];
    __shared__ int   smask[256];
    __shared__ float smx[2][128], ssm[2][128];

    const int t = threadIdx.x, wid = t >> 5, lane = t & 31;
    const int gid = lane >> 2, tig = lane & 3;
    const int nbase = blockIdx.x * 256, m0 = blockIdx.y * 128;
    const int bh = blockIdx.z, b = bh / H_;
    const int wm = (wid & 3) * 32, wn = (wid >> 2) * 32;
    const int hf = wid >> 2;

    const int a_r = lane & 15, a_c = ((lane >> 4) & 1) * 4;
    const int b_r = (lane & 7) + ((lane >> 4) & 1) * 8;
    const int b_c = ((lane >> 3) & 1) * 4;

    smask[t] = mask[b * S_ + nbase + t];

    const int br = t >> 2, bg = t & 3;

    // ---- A: load full K=64 into smem (slab = t&1, row = t>>1)
    {
        const int slab = t & 1, row = t >> 1;
        const float* Qb = Qp + ((size_t)bh * S_ + m0 + row) * DEP_ + slab * 32;
        unsigned* AH = dsm + slab * 2560;
        unsigned* AL = dsm + 5120 + slab * 2560;
#pragma unroll
        for (int g = 0; g < 4; g++) {
            float4 f0 = *(const float4*)(Qb + g * 8);
            float4 f1 = *(const float4*)(Qb + g * 8 + 4);
            unsigned h, l;
            split2(f0.x, f0.y, h, l);
            AH[row*20 + g*4 + 0] = h;  AL[row*20 + g*4 + 0] = l;
            split2(f0.z, f0.w, h, l);
            AH[row*20 + g*4 + 1] = h;  AL[row*20 + g*4 + 1] = l;
            split2(f1.x, f1.y, h, l);
            AH[row*20 + g*4 + 2] = h;  AL[row*20 + g*4 + 2] = l;
            split2(f1.z, f1.w, h, l);
            AH[row*20 + g*4 + 3] = h;  AL[row*20 + g*4 + 3] = l;
        }
    }

    // ---- B it=0 load + store into stage 0
    float4 wb[2];
    {
        const float* Kb = Kp + ((size_t)bh * S_ + nbase + br) * DEP_ + bg * 8;
#pragma unroll
        for (int j = 0; j < 2; j++) wb[j] = *(const float4*)(Kb + j * 4);
        unsigned* BH = dsm + 10240;
        unsigned* BL = dsm + 10240 + 1280;
#pragma unroll
        for (int j = 0; j < 2; j++) {
            unsigned h, l;
            split2(wb[j].x, wb[j].y, h, l);
            BH[br*20 + bg*4 + 2*j]   = h;  BL[br*20 + bg*4 + 2*j]   = l;
            split2(wb[j].z, wb[j].w, h, l);
            BH[br*20 + bg*4 + 2*j+1] = h;  BL[br*20 + bg*4 + 2*j+1] = l;
        }
    }
    __syncthreads();

    float runm[2][2], runs[2][2];
#pragma unroll
    for (int i = 0; i < 2; i++)
#pragma unroll
        for (int j = 0; j < 2; j++) { runm[i][j] = neg_inf(); runs[i][j] = 0.0f; }

    float acc[2][4][4];
    float* Cb = attn + (size_t)bh * S_ * S_;

#pragma unroll
    for (int it = 0; it < 8; it++) {
        const int ni = it >> 1, ks = it & 1, st = it & 1;
        if (ks == 0) {
#pragma unroll
            for (int i = 0; i < 2; i++)
#pragma unroll
                for (int j = 0; j < 4; j++)
#pragma unroll
                    for (int q = 0; q < 4; q++) acc[i][j][q] = 0.0f;
        }

        if (it + 1 < 8) {
            const int niN = (it+1) >> 1, ksN = (it+1) & 1;
            const float* Kb = Kp + ((size_t)bh * S_ + nbase + niN*64 + br) * DEP_
                              + ksN*32 + bg*8;
#pragma unroll
            for (int j = 0; j < 2; j++) wb[j] = *(const float4*)(Kb + j * 4);
        }

        // ---- mma: A slab ks, B stage st
#pragma unroll
        for (int step = 0; step < 2; step++) {
            const int kc = step * 8;
            unsigned ah[2][4], al[2][4], bhf[2][4], blf[2][4];
#pragma unroll
            for (int mt = 0; mt < 2; mt++) {
                ldsm_x4(ah[mt], dsm + ks*2560        + (wm + mt*16 + a_r)*20 + kc + a_c);
                ldsm_x4(al[mt], dsm + 5120 + ks*2560 + (wm + mt*16 + a_r)*20 + kc + a_c);
            }
#pragma unroll
            for (int np = 0; np < 2; np++) {
                ldsm_x4(bhf[np], dsm + 10240 + st*2560        + (wn + np*16 + b_r)*20 + kc + b_c);
                ldsm_x4(blf[np], dsm + 10240 + st*2560 + 1280 + (wn + np*16 + b_r)*20 + kc + b_c);
            }
            MMA_STEP_PRODMAJOR(acc, ah, al, bhf, blf);
        }

        if (ks == 1) {
            bool mz[4][2];
#pragma unroll
            for (int nt = 0; nt < 4; nt++) {
                const int lc = ni*64 + wn + nt*8 + tig*2;
                mz[nt][0] = (smask[lc] == 0);
                mz[nt][1] = (smask[lc+1] == 0);
            }
#pragma unroll
            for (int mt = 0; mt < 2; mt++) {
#pragma unroll
                for (int nt = 0; nt < 4; nt++) {
                    const int r0 = m0 + wm + mt*16 + gid;
                    const int r1 = r0 + 8;
                    const int c  = nbase + ni*64 + wn + nt*8 + tig*2;
                    float2 v0, v1;
                    v0.x = mz[nt][0] ? neg_inf() : acc[mt][nt][0];
                    v0.y = mz[nt][1] ? neg_inf() : acc[mt][nt][1];
                    v1.x = mz[nt][0] ? neg_inf() : acc[mt][nt][2];
                    v1.y = mz[nt][1] ? neg_inf() : acc[mt][nt][3];
                    *(float2*)(Cb + (size_t)r0 * S_ + c) = v0;
                    *(float2*)(Cb + (size_t)r1 * S_ + c) = v1;
                }
            }
#pragma unroll
            for (int mt = 0; mt < 2; mt++) {
#pragma unroll
                for (int rh = 0; rh < 2; rh++) {
                    float mx = neg_inf();
#pragma unroll
                    for (int nt = 0; nt < 4; nt++) {
                        float v0 = mz[nt][0] ? neg_inf() : acc[mt][nt][rh*2];
                        float v1 = mz[nt][1] ? neg_inf() : acc[mt][nt][rh*2+1];
                        mx = fmaxf(mx, fmaxf(v0, v1));
                    }
                    mx = fmaxf(mx, __shfl_xor_sync(0xffffffffu, mx, 1));
                    mx = fmaxf(mx, __shfl_xor_sync(0xffffffffu, mx, 2));
                    float s = 0.0f;
                    if (mx != neg_inf()) {
#pragma unroll
                        for (int nt = 0; nt < 4; nt++) {
                            if (!mz[nt][0]) s += __expf(acc[mt][nt][rh*2]   - mx);
                            if (!mz[nt][1]) s += __expf(acc[mt][nt][rh*2+1] - mx);
                        }
                    }
                    s += __shfl_xor_sync(0xffffffffu, s, 1);
                    s += __shfl_xor_sync(0xffffffffu, s, 2);
                    if (mx > runm[mt][rh]) {
                        runs[mt][rh] = runs[mt][rh] * __expf(runm[mt][rh] - mx) + s;
                        runm[mt][rh] = mx;
                    } else if (mx != neg_inf()) {
                        runs[mt][rh] += s * __expf(mx - runm[mt][rh]);
                    }
                }
            }
        }

        // ---- store B it+1 into stage st^1
        if (it + 1 < 8) {
            unsigned* BH = dsm + 10240 + (st^1)*2560;
            unsigned* BL = BH + 1280;
#pragma unroll
            for (int j = 0; j < 2; j++) {
                unsigned h, l;
                split2(wb[j].x, wb[j].y, h, l);
                BH[br*20 + bg*4 + 2*j]   = h;  BL[br*20 + bg*4 + 2*j]   = l;
                split2(wb[j].z, wb[j].w, h, l);
                BH[br*20 + bg*4 + 2*j+1] = h;  BL[br*20 + bg*4 + 2*j+1] = l;
            }
        }
        __syncthreads();
    }

    // ---- cross-half combine + write chunk partials
    if (tig == 0) {
#pragma unroll
        for (int mt = 0; mt < 2; mt++)
#pragma unroll
            for (int rh = 0; rh < 2; rh++) {
                const int row = wm + mt*16 + rh*8 + gid;
                smx[hf][row] = runm[mt][rh];
                ssm[hf][row] = runs[mt][rh];
            }
    }
    __syncthreads();
    if (t < 128) {
        const float m0v = smx[0][t], m1v = smx[1][t];
        const float s0 = ssm[0][t], s1 = ssm[1][t];
        const float M = fmaxf(m0v, m1v);
        float S = 0.0f;
        if (m0v != neg_inf()) S += s0 * __expf(m0v - M);
        if (m1v != neg_inf()) S += s1 * __expf(m1v - M);
        const size_t row = (size_t)bh * S_ + m0 + t;
        cmax[row * NCHUNK + blockIdx.x] = M;
        csum[row * NCHUNK + blockIdx.x] = S;
    }
}

// ======================================================================
__global__ __launch_bounds__(256)
void chunk_reduce(const float* __restrict__ cmax,
                  const float* __restrict__ csum,
                  float* __restrict__ gmax,
                  float* __restrict__ ginv)
{
    const int r = blockIdx.x * 256 + threadIdx.x;
    if (r >= BH_ * S_) return;
    float M = neg_inf(), S = 0.0f;
#pragma unroll
    for (int c = 0; c < NCHUNK; c++) {
        const float m = cmax[(size_t)r * NCHUNK + c];
        const float s = csum[(size_t)r * NCHUNK + c];
        if (m > M) { S = S * __expf(M - m) + s; M = m; }
        else if (m != neg_inf()) { S += s * __expf(m - M); }
    }
    gmax[r] = M;
    ginv[r] = 1.0f / S;
}

// ======================================================================
// ctx: double-buffered A and V stages, ONE sync per 32-n slab.
// dyn smem (words): A stage st: AH @ st*5120, AL @ st*5120+2560;
//   V stage st: VH @ 10240 + st*2560, VL @ +1280. grid (16, 24)
// ======================================================================
__global__ __launch_bounds__(256, 2)
void ctx_bf16(float* __restrict__ attn,
              const unsigned* __restrict__ Vth,
              const unsigned* __restrict__ Vtl,
              const float* __restrict__ gmax,
              const float* __restrict__ ginv,
              float* __restrict__ ctx)
{
    extern __shared__ unsigned dsm[];

    const int t = threadIdx.x, wid = t >> 5, lane = t & 31;
    const int gid = lane >> 2, tig = lane & 3;
    const int m0 = blockIdx.x * 128;
    const int bh = blockIdx.y;
    const int b  = bh / H_, h = bh % H_;
    const int wm = (wid & 3) * 32, wd = (wid >> 2) * 32;

    const int a_r = lane & 15, a_c = ((lane >> 4) & 1) * 4;
    const int b_r = (lane & 7) + ((lane >> 4) & 1) * 8;
    const int b_c = ((lane >> 3) & 1) * 4;

    const int lr = t >> 1, lg = t & 1;
    const int vr = t >> 2, vg = t & 3;

    float* Ap = attn + ((size_t)bh * S_ + m0 + lr) * S_ + lg * 16;
    const unsigned* VthB = Vth + ((size_t)bh * DEP_ + vr) * (S_/2) + vg * 4;
    const unsigned* VtlB = Vtl + ((size_t)bh * DEP_ + vr) * (S_/2) + vg * 4;

    const float mr = gmax[bh * S_ + m0 + lr];
    const float ir = ginv[bh * S_ + m0 + lr];

    float acc[2][4][4];
#pragma unroll
    for (int i = 0; i < 2; i++)
#pragma unroll
        for (int j = 0; j < 4; j++)
#pragma unroll
            for (int q = 0; q < 4; q++) acc[i][j][q] = 0.0f;

    float4 av[4];
    uint4 vh4, vl4;

    // ---- prologue: slab 0 -> stage 0
#pragma unroll
    for (int j = 0; j < 4; j++) av[j] = *(const float4*)(Ap + j * 4);
    vh4 = *(const uint4*)(VthB);
    vl4 = *(const uint4*)(VtlB);
    {
        unsigned* AH = dsm;          unsigned* AL = dsm + 2560;
        unsigned* VH = dsm + 10240;  unsigned* VL = dsm + 10240 + 1280;
#pragma unroll
        for (int j = 0; j < 4; j++) {
            float4 pv;
            pv.x = __expf(av[j].x - mr) * ir;
            pv.y = __expf(av[j].y - mr) * ir;
            pv.z = __expf(av[j].z - mr) * ir;
            pv.w = __expf(av[j].w - mr) * ir;
            *(float4*)(Ap + j * 4) = pv;
            unsigned hh, ll;
            split2(pv.x, pv.y, hh, ll);
            AH[lr*20 + lg*8 + 2*j]   = hh;  AL[lr*20 + lg*8 + 2*j]   = ll;
            split2(pv.z, pv.w, hh, ll);
            AH[lr*20 + lg*8 + 2*j+1] = hh;  AL[lr*20 + lg*8 + 2*j+1] = ll;
        }
        *(uint4*)&VH[vr*20 + vg*4] = vh4;
        *(uint4*)&VL[vr*20 + vg*4] = vl4;
    }
    __syncthreads();

#pragma unroll 1
    for (int i = 0; i < 64; i++) {
        const int st = i & 1;

        if (i + 1 < 64) {
            const int nc = (i + 1) * 32;
#pragma unroll
            for (int j = 0; j < 4; j++) av[j] = *(const float4*)(Ap + nc + j * 4);
            vh4 = *(const uint4*)(VthB + nc/2);
            vl4 = *(const uint4*)(VtlB + nc/2);
        }

        // ---- mma from stage st
#pragma unroll
        for (int step = 0; step < 2; step++) {
            const int kc = step * 8;
            unsigned ah[2][4], al[2][4], bhf[2][4], blf[2][4];
#pragma unroll
            for (int mt = 0; mt < 2; mt++) {
                ldsm_x4(ah[mt], dsm + st*5120        + (wm + mt*16 + a_r)*20 + kc + a_c);
                ldsm_x4(al[mt], dsm + st*5120 + 2560 + (wm + mt*16 + a_r)*20 + kc + a_c);
            }
#pragma unroll
            for (int np = 0; np < 2; np++) {
                ldsm_x4(bhf[np], dsm + 10240 + st*2560        + (wd + np*16 + b_r)*20 + kc + b_c);
                ldsm_x4(blf[np], dsm + 10240 + st*2560 + 1280 + (wd + np*16 + b_r)*20 + kc + b_c);
            }
            MMA_STEP_PRODMAJOR(acc, ah, al, bhf, blf);
        }

        // ---- process slab i+1 -> stage st^1
        if (i + 1 < 64) {
            const int nc = (i + 1) * 32;
            const unsigned ab = (st ^ 1) * 5120;
            unsigned* AH = dsm + ab;            unsigned* AL = dsm + ab + 2560;
            unsigned* VH = dsm + 10240 + (st^1)*2560;
            unsigned* VL = VH + 1280;
#pragma unroll
            for (int j = 0; j < 4; j++) {
                float4 pv;
                pv.x = __expf(av[j].x - mr) * ir;
                pv.y = __expf(av[j].y - mr) * ir;
                pv.z = __expf(av[j].z - mr) * ir;
                pv.w = __expf(av[j].w - mr) * ir;
                *(float4*)(Ap + nc + j * 4) = pv;
                unsigned hh, ll;
                split2(pv.x, pv.y, hh, ll);
                AH[lr*20 + lg*8 + 2*j]   = hh;  AL[lr*20 + lg*8 + 2*j]   = ll;
                split2(pv.z, pv.w, hh, ll);
                AH[lr*20 + lg*8 + 2*j+1] = hh;  AL[lr*20 + lg*8 + 2*j+1] = ll;
            }
            *(uint4*)&VH[vr*20 + vg*4] = vh4;
            *(uint4*)&VL[vr*20 + vg*4] = vl4;
        }
        __syncthreads();
    }

#pragma unroll
    for (int mt = 0; mt < 2; mt++) {
#pragma unroll
        for (int dt = 0; dt < 4; dt++) {
            const int r0 = m0 + wm + mt*16 + gid;
            const int r1 = r0 + 8;
            const int d  = wd + dt*8 + tig*2;
            float2 v0 = {acc[mt][dt][0], acc[mt][dt][1]};
            float2 v1 = {acc[mt][dt][2], acc[mt][dt][3]};
            *(float2*)(ctx + ((size_t)b * S_ + r0) * D_ + h * DEP_ + d) = v0;
            *(float2*)(ctx + ((size_t)b * S_ + r1) * D_ + h * DEP_ + d) = v1;
        }
    }
}

// ======================================================================
extern "C" void kernel_launch(void* const* d_in, const int* in_sizes, int n_in,
                              void* d_out, int out_size)
{
    const float* q    = (const float*)d_in[0];
    const float* k    = (const float*)d_in[1];
    const float* v    = (const float*)d_in[2];
    const int*   mask = (const int*)  d_in[3];
    const float* wq_w = (const float*)d_in[4];
    const float* wq_b = (const float*)d_in[5];
    const float* wk_w = (const float*)d_in[6];
    const float* wk_b = (const float*)d_in[7];
    const float* wv_w = (const float*)d_in[8];
    const float* wv_b = (const float*)d_in[9];
    const float* wo_w = (const float*)d_in[10];
    const float* wo_b = (const float*)d_in[11];
    float* out = (float*)d_out;

    float *Qp, *Kp, *ctxp, *rmax, *rinv, *cmax, *csum, *attn_s;
    unsigned *Vth, *Vtl;
    cudaGetSymbolAddress((void**)&Qp,     g_Qp);
    cudaGetSymbolAddress((void**)&Kp,     g_Kp);
    cudaGetSymbolAddress((void**)&ctxp,   g_ctx);
    cudaGetSymbolAddress((void**)&rmax,   g_rowmax);
    cudaGetSymbolAddress((void**)&rinv,   g_rowinv);
    cudaGetSymbolAddress((void**)&cmax,   g_cmax);
    cudaGetSymbolAddress((void**)&csum,   g_csum);
    cudaGetSymbolAddress((void**)&Vth,    g_Vth);
    cudaGetSymbolAddress((void**)&Vtl,    g_Vtl);
    cudaGetSymbolAddress((void**)&attn_s, g_attn_scratch);

    const long long need = (long long)OUT_ELEMS + (long long)ATTN_ELEMS;
    float* attn = ((long long)out_size >= need) ? (out + OUT_ELEMS) : attn_s;

    cudaFuncSetAttribute(gemm_xwT_bf16,
                         cudaFuncAttributeMaxDynamicSharedMemorySize, DYN_SMEM_BYTES);
    cudaFuncSetAttribute(logits_bf16,
                         cudaFuncAttributeMaxDynamicSharedMemorySize, DYN_SMEM_BYTES);
    cudaFuncSetAttribute(ctx_bf16,
                         cudaFuncAttributeMaxDynamicSharedMemorySize, DYN_SMEM_BYTES);

    // Fused Q/K/V projections in ONE launch (grid.z = 3); V writes split
    // transposed Vth/Vtl directly (mode 3 path via z==2).
    dim3 pgrid3(D_/64, MROWS/128, 3);
    gemm_xwT_bf16<<<pgrid3, 256, DYN_SMEM_BYTES>>>(
        q, k, v, wq_w, wk_w, wv_w, wq_b, wk_b, wv_b,
        Qp, Kp, Vth, Vtl, D_, D_, 1);

    // raw masked logits + per-chunk softmax partials
    logits_bf16<<<dim3(S_/256, S_/128, BH_), 256, DYN_SMEM_BYTES>>>(
        Qp, Kp, mask, attn, cmax, csum);

    // combine partials -> row stats
    chunk_reduce<<<dim3((BH_*S_ + 255)/256), 256>>>(cmax, csum, rmax, rinv);

    // ctx = softmax @ V; normalizes attn in place
    ctx_bf16<<<dim3(S_/128, BH_), 256, DYN_SMEM_BYTES>>>(
        attn, Vth, Vtl, rmax, rinv, ctxp);

    // output projection (fused=0 -> mode 0, alpha 1; uses z==0 operands)
    dim3 pgrid1(D_/64, MROWS/128, 1);
    gemm_xwT_bf16<<<pgrid1, 256, DYN_SMEM_BYTES>>>(
        ctxp, nullptr, nullptr, wo_w, nullptr, nullptr, wo_b, nullptr, nullptr,
        out, nullptr, nullptr, nullptr, D_, D_, 0);
}